// round 2
// baseline (speedup 1.0000x reference)
#include <cuda_runtime.h>
#include <cuda_bf16.h>
#include <math.h>

// ---------------------------------------------------------------------------
// Problem constants
// ---------------------------------------------------------------------------
#define DEPTH   4
#define HEADS   8
#define DIM     512
#define HIDDEN  1024
#define NTOK    17
#define BATCH   2048
#define MTOT    (BATCH * NTOK)          // 34816 tokens, divisible by 128
#define KHOPS   4

// ---------------------------------------------------------------------------
// Scratch (device globals: no allocation allowed in kernel_launch)
// ---------------------------------------------------------------------------
__device__ float g_h  [(size_t)MTOT * DIM];      //  71 MB: LN out / attn out
__device__ float g_big[(size_t)MTOT * 3 * DIM];  // 214 MB: qkv, reused as MLP hidden
__device__ float g_bias[HEADS * NTOK * NTOK];    // hop bias, layer-invariant

// ---------------------------------------------------------------------------
// Hop-bias precompute: bias[h,i,j] = rel_alpha[h] * sum_k softmax(hop)[h,k]*H[k,i,j]
// ---------------------------------------------------------------------------
__global__ void bias_kernel(const float* __restrict__ Hstack,
                            const float* __restrict__ hop,
                            const float* __restrict__ rel) {
    int h = blockIdx.x;
    float l0 = hop[h*KHOPS+0], l1 = hop[h*KHOPS+1], l2 = hop[h*KHOPS+2], l3 = hop[h*KHOPS+3];
    float m = fmaxf(fmaxf(l0, l1), fmaxf(l2, l3));
    float e0 = expf(l0-m), e1 = expf(l1-m), e2 = expf(l2-m), e3 = expf(l3-m);
    float inv = 1.0f / (e0+e1+e2+e3);
    float w0 = e0*inv, w1 = e1*inv, w2 = e2*inv, w3 = e3*inv;
    int ij = threadIdx.x;
    if (ij < NTOK*NTOK) {
        float a = w0*Hstack[0*289+ij] + w1*Hstack[1*289+ij]
                + w2*Hstack[2*289+ij] + w3*Hstack[3*289+ij];
        g_bias[h*289 + ij] = rel[h] * a;
    }
}

// ---------------------------------------------------------------------------
// LayerNorm: one block per token, 128 threads, float4 per thread (C=512)
// ---------------------------------------------------------------------------
__global__ void ln_kernel(const float* __restrict__ x,
                          const float* __restrict__ g,
                          const float* __restrict__ b,
                          float* __restrict__ o) {
    const size_t base = (size_t)blockIdx.x * DIM;
    const int t = threadIdx.x;
    float4 v = *(const float4*)(x + base + t*4);
    float s = v.x + v.y + v.z + v.w;
    float q = v.x*v.x + v.y*v.y + v.z*v.z + v.w*v.w;
    #pragma unroll
    for (int off = 16; off; off >>= 1) {
        s += __shfl_xor_sync(0xffffffffu, s, off);
        q += __shfl_xor_sync(0xffffffffu, q, off);
    }
    __shared__ float sw[4], qw[4];
    int w = t >> 5, l = t & 31;
    if (l == 0) { sw[w] = s; qw[w] = q; }
    __syncthreads();
    float S = sw[0]+sw[1]+sw[2]+sw[3];
    float Q = qw[0]+qw[1]+qw[2]+qw[3];
    float mean = S * (1.0f/512.0f);
    float var  = Q * (1.0f/512.0f) - mean*mean;
    float r = rsqrtf(var + 1e-5f);
    float4 gg = *(const float4*)(g + t*4);
    float4 bb = *(const float4*)(b + t*4);
    float4 ov;
    ov.x = (v.x-mean)*r*gg.x + bb.x;
    ov.y = (v.y-mean)*r*gg.y + bb.y;
    ov.z = (v.z-mean)*r*gg.z + bb.z;
    ov.w = (v.w-mean)*r*gg.w + bb.w;
    *(float4*)(o + base + t*4) = ov;
}

// ---------------------------------------------------------------------------
// Attention: grid (BATCH, HEADS), 128 threads. N=17, hd=64.
// qkv layout: [token, 3*512] with q at h*64, k at 512+h*64, v at 1024+h*64.
// k stored transposed in smem (kt4[16][17] of float4) for conflict-free dots.
// ---------------------------------------------------------------------------
__global__ void attn_kernel(const float* __restrict__ qkv,
                            float* __restrict__ out) {
    const int b = blockIdx.x, h = blockIdx.y;
    __shared__ float  qs[NTOK][64];
    __shared__ float  vs[NTOK][64];
    __shared__ float4 kt4[16][NTOK];
    const int t = threadIdx.x;
    const float* base = qkv + (size_t)b * NTOK * (3*DIM) + h * 64;

    for (int idx = t; idx < NTOK*16; idx += 128) {
        int n = idx >> 4, c = idx & 15;
        const float* p = base + (size_t)n * (3*DIM) + c*4;
        *(float4*)&qs[n][c*4] = *(const float4*)p;
        *(float4*)&vs[n][c*4] = *(const float4*)(p + 2*DIM);
        kt4[c][n]             = *(const float4*)(p + DIM);
    }
    __syncthreads();

    const int warp = t >> 5, lane = t & 31;
    for (int i = warp; i < NTOK; i += 4) {
        float logit = -INFINITY;
        if (lane < NTOK) {
            float s = 0.0f;
            #pragma unroll
            for (int c = 0; c < 16; c++) {
                float4 qv = *(const float4*)&qs[i][c*4];
                float4 kv = kt4[c][lane];
                s += qv.x*kv.x + qv.y*kv.y + qv.z*kv.z + qv.w*kv.w;
            }
            logit = s * 0.125f + g_bias[h*289 + i*NTOK + lane];
        }
        float mx = logit;
        #pragma unroll
        for (int off = 16; off; off >>= 1)
            mx = fmaxf(mx, __shfl_xor_sync(0xffffffffu, mx, off));
        float e = (lane < NTOK) ? __expf(logit - mx) : 0.0f;
        float sum = e;
        #pragma unroll
        for (int off = 16; off; off >>= 1)
            sum += __shfl_xor_sync(0xffffffffu, sum, off);
        float p = e / sum;

        float a0 = 0.0f, a1 = 0.0f;
        #pragma unroll
        for (int j = 0; j < NTOK; j++) {
            float pj = __shfl_sync(0xffffffffu, p, j);
            a0 += pj * vs[j][lane];
            a1 += pj * vs[j][lane + 32];
        }
        float* op = out + ((size_t)(b*NTOK + i)) * DIM + h * 64;
        op[lane]      = a0;
        op[lane + 32] = a1;
    }
}

// ---------------------------------------------------------------------------
// SGEMM (NT): C[m,n] = sum_k A[m,k]*B[n,k]  (+bias, +gelu, +residual)
// A [M,K] row-major, B [N,K] row-major. 128x128x16 tile, 256 threads,
// 8x8 per thread with packed fp32x2 FMA (fma.rn.f32x2 -> FFMA2).
// mode: 1 = +bias, 2 = +bias+gelu(exact), 3 = +bias+residual
// ---------------------------------------------------------------------------
#define BM 128
#define BN 128
#define BK 16

__device__ __forceinline__ float gelu_exact(float x) {
    return 0.5f * x * (1.0f + erff(x * 0.70710678118654752f));
}

#define STORE_TILE(buf) do {                                          \
    float* pa = &As[buf][0][0] + lcol*BM + lrow;                      \
    pa[0*BM]    = a0.x; pa[1*BM]    = a0.y;                           \
    pa[2*BM]    = a0.z; pa[3*BM]    = a0.w;                           \
    pa[0*BM+64] = a1.x; pa[1*BM+64] = a1.y;                           \
    pa[2*BM+64] = a1.z; pa[3*BM+64] = a1.w;                           \
    float* pb = &Bs[buf][0][0] + lcol*BN + lrow;                      \
    pb[0*BN]    = b0.x; pb[1*BN]    = b0.y;                           \
    pb[2*BN]    = b0.z; pb[3*BN]    = b0.w;                           \
    pb[0*BN+64] = b1.x; pb[1*BN+64] = b1.y;                           \
    pb[2*BN+64] = b1.z; pb[3*BN+64] = b1.w;                           \
} while (0)

__global__ __launch_bounds__(256, 2) void sgemm_nt(
    const float* __restrict__ A, const float* __restrict__ B,
    const float* __restrict__ bias, const float* __restrict__ res,
    float* __restrict__ C, int N, int K, int mode)
{
    __shared__ float As[2][BK][BM];
    __shared__ float Bs[2][BK][BN];

    const int bm = blockIdx.y * BM;
    const int bn = blockIdx.x * BN;
    const int tid = threadIdx.x;

    // global-load mapping: 2 float4 from A, 2 from B per thread
    const int lrow = tid >> 2;            // 0..63
    const int lcol = (tid & 3) << 2;      // 0,4,8,12
    const float* Ag = A + (size_t)(bm + lrow) * K + lcol;
    const float* Bg = B + (size_t)(bn + lrow) * K + lcol;

    // compute mapping: 8 warps in 4x2, 8x8 per thread
    const int warp = tid >> 5;
    const int lane = tid & 31;
    const int tm = (warp & 3) * 32 + (lane & 3) * 8;
    const int tn = (warp >> 2) * 64 + (lane >> 2) * 8;

    unsigned long long acc[8][4];
    #pragma unroll
    for (int i = 0; i < 8; i++)
        #pragma unroll
        for (int j = 0; j < 4; j++) acc[i][j] = 0ULL;

    float4 a0, a1, b0, b1;
    a0 = *(const float4*)Ag;
    a1 = *(const float4*)(Ag + (size_t)64 * K);
    b0 = *(const float4*)Bg;
    b1 = *(const float4*)(Bg + (size_t)64 * K);
    STORE_TILE(0);
    __syncthreads();

    const int nt = K / BK;
    for (int t = 0; t < nt; ++t) {
        const int cur = t & 1;
        if (t + 1 < nt) {
            const float* Ap = Ag + (size_t)(t + 1) * BK;
            const float* Bp = Bg + (size_t)(t + 1) * BK;
            a0 = *(const float4*)Ap;
            a1 = *(const float4*)(Ap + (size_t)64 * K);
            b0 = *(const float4*)Bp;
            b1 = *(const float4*)(Bp + (size_t)64 * K);
        }
        #pragma unroll
        for (int kk = 0; kk < BK; ++kk) {
            float ra[8];
            *(float4*)&ra[0] = *(const float4*)&As[cur][kk][tm];
            *(float4*)&ra[4] = *(const float4*)&As[cur][kk][tm + 4];
            ulonglong2 rb0 = *(const ulonglong2*)&Bs[cur][kk][tn];
            ulonglong2 rb1 = *(const ulonglong2*)&Bs[cur][kk][tn + 4];
            unsigned long long bp0 = rb0.x, bp1 = rb0.y, bp2 = rb1.x, bp3 = rb1.y;
            #pragma unroll
            for (int i = 0; i < 8; i++) {
                unsigned long long a2;
                unsigned int au = __float_as_uint(ra[i]);
                asm("mov.b64 %0, {%1, %1};" : "=l"(a2) : "r"(au));
                asm("fma.rn.f32x2 %0, %1, %2, %0;" : "+l"(acc[i][0]) : "l"(a2), "l"(bp0));
                asm("fma.rn.f32x2 %0, %1, %2, %0;" : "+l"(acc[i][1]) : "l"(a2), "l"(bp1));
                asm("fma.rn.f32x2 %0, %1, %2, %0;" : "+l"(acc[i][2]) : "l"(a2), "l"(bp2));
                asm("fma.rn.f32x2 %0, %1, %2, %0;" : "+l"(acc[i][3]) : "l"(a2), "l"(bp3));
            }
        }
        if (t + 1 < nt) {
            const int nx = cur ^ 1;
            STORE_TILE(nx);
        }
        __syncthreads();
    }

    // ---------------- epilogue ----------------
    float bv[8];
    *(float4*)&bv[0] = *(const float4*)&bias[bn + tn];
    *(float4*)&bv[4] = *(const float4*)&bias[bn + tn + 4];

    #pragma unroll
    for (int i = 0; i < 8; i++) {
        size_t row = (size_t)(bm + tm + i) * N + bn + tn;
        float o[8];
        #pragma unroll
        for (int j = 0; j < 4; j++) {
            float2 f = *(float2*)&acc[i][j];
            o[2*j]   = f.x + bv[2*j];
            o[2*j+1] = f.y + bv[2*j+1];
        }
        if (mode == 2) {
            #pragma unroll
            for (int j = 0; j < 8; j++) o[j] = gelu_exact(o[j]);
        } else if (mode == 3) {
            float4 r0 = *(const float4*)&res[row];
            float4 r1 = *(const float4*)&res[row + 4];
            o[0] += r0.x; o[1] += r0.y; o[2] += r0.z; o[3] += r0.w;
            o[4] += r1.x; o[5] += r1.y; o[6] += r1.z; o[7] += r1.w;
        }
        *(float4*)&C[row]     = make_float4(o[0], o[1], o[2], o[3]);
        *(float4*)&C[row + 4] = make_float4(o[4], o[5], o[6], o[7]);
    }
}

// ---------------------------------------------------------------------------
// kernel_launch
// Inputs (metadata order): x, Hstack, hop_logits_attn, rel_alpha,
//   qkv_w, qkv_b, proj_w, proj_b, ln1_g, ln1_b, ln2_g, ln2_b,
//   fc1_w, fc1_b, fc2_w, fc2_b
// ---------------------------------------------------------------------------
extern "C" void kernel_launch(void* const* d_in, const int* in_sizes, int n_in,
                              void* d_out, int out_size) {
    const float* x      = (const float*)d_in[0];
    const float* Hstack = (const float*)d_in[1];
    const float* hop    = (const float*)d_in[2];
    const float* rel    = (const float*)d_in[3];
    const float* qkv_w  = (const float*)d_in[4];
    const float* qkv_b  = (const float*)d_in[5];
    const float* proj_w = (const float*)d_in[6];
    const float* proj_b = (const float*)d_in[7];
    const float* ln1_g  = (const float*)d_in[8];
    const float* ln1_b  = (const float*)d_in[9];
    const float* ln2_g  = (const float*)d_in[10];
    const float* ln2_b  = (const float*)d_in[11];
    const float* fc1_w  = (const float*)d_in[12];
    const float* fc1_b  = (const float*)d_in[13];
    const float* fc2_w  = (const float*)d_in[14];
    const float* fc2_b  = (const float*)d_in[15];
    float* out = (float*)d_out;

    float *h, *big;
    cudaGetSymbolAddress((void**)&h,   g_h);
    cudaGetSymbolAddress((void**)&big, g_big);

    // running x lives in d_out
    cudaMemcpyAsync(out, x, (size_t)MTOT * DIM * sizeof(float),
                    cudaMemcpyDeviceToDevice, 0);

    bias_kernel<<<HEADS, NTOK * NTOK>>>(Hstack, hop, rel);

    const dim3 gemm_thr(256);
    for (int d = 0; d < DEPTH; d++) {
        // LN1
        ln_kernel<<<MTOT, 128>>>(out, ln1_g + d*DIM, ln1_b + d*DIM, h);
        // qkv = h @ qkv_w.T + qkv_b   -> big [MTOT, 1536]
        sgemm_nt<<<dim3(3*DIM/BN, MTOT/BM), gemm_thr>>>(
            h, qkv_w + (size_t)d*3*DIM*DIM, qkv_b + (size_t)d*3*DIM,
            nullptr, big, 3*DIM, DIM, 1);
        // attention -> h [MTOT, 512]
        attn_kernel<<<dim3(BATCH, HEADS), 128>>>(big, h);
        // x += attn @ proj_w.T + proj_b
        sgemm_nt<<<dim3(DIM/BN, MTOT/BM), gemm_thr>>>(
            h, proj_w + (size_t)d*DIM*DIM, proj_b + (size_t)d*DIM,
            out, out, DIM, DIM, 3);
        // LN2
        ln_kernel<<<MTOT, 128>>>(out, ln2_g + d*DIM, ln2_b + d*DIM, h);
        // h2 = gelu(h @ fc1_w.T + fc1_b)  -> big [MTOT, 1024]
        sgemm_nt<<<dim3(HIDDEN/BN, MTOT/BM), gemm_thr>>>(
            h, fc1_w + (size_t)d*HIDDEN*DIM, fc1_b + (size_t)d*HIDDEN,
            nullptr, big, HIDDEN, DIM, 2);
        // x += h2 @ fc2_w.T + fc2_b
        sgemm_nt<<<dim3(DIM/BN, MTOT/BM), gemm_thr>>>(
            big, fc2_w + (size_t)d*DIM*HIDDEN, fc2_b + (size_t)d*DIM,
            out, out, DIM, HIDDEN, 3);
    }
}

// round 7
// speedup vs baseline: 2.1924x; 2.1924x over previous
#include <cuda_runtime.h>
#include <cuda_bf16.h>
#include <math.h>
#include <stdint.h>

// ---------------------------------------------------------------------------
// Problem constants
// ---------------------------------------------------------------------------
#define DEPTH   4
#define HEADS   8
#define DIM     512
#define HIDDEN  1024
#define NTOK    17
#define BATCH   2048
#define MTOT    (BATCH * NTOK)          // 34816 tokens (272 * 128)
#define KHOPS   4

// weight-split buffer offsets (elements)
#define WQKV_PER  (3*DIM*DIM)
#define WQKV_OFF  0
#define WPROJ_PER (DIM*DIM)
#define WPROJ_OFF (4*WQKV_PER)
#define WFC1_PER  (HIDDEN*DIM)
#define WFC1_OFF  (WPROJ_OFF + 4*WPROJ_PER)
#define WFC2_PER  (DIM*HIDDEN)
#define WFC2_OFF  (WFC1_OFF + 4*WFC1_PER)
#define WTOT      (WFC2_OFF + 4*WFC2_PER)

// ---------------------------------------------------------------------------
// Scratch (device globals)
// ---------------------------------------------------------------------------
__device__ float         g_big [(size_t)MTOT * 3 * DIM];   // qkv fp32
__device__ __nv_bfloat16 g_ah  [(size_t)MTOT * DIM];       // activation hi
__device__ __nv_bfloat16 g_al  [(size_t)MTOT * DIM];       // activation lo
__device__ __nv_bfloat16 g_bh  [(size_t)MTOT * HIDDEN];    // mlp hidden hi
__device__ __nv_bfloat16 g_bl  [(size_t)MTOT * HIDDEN];    // mlp hidden lo
__device__ __nv_bfloat16 g_wh  [WTOT];                     // weights hi
__device__ __nv_bfloat16 g_wl  [WTOT];                     // weights lo
__device__ float         g_bias[HEADS * NTOK * NTOK];      // hop bias

// ---------------------------------------------------------------------------
// PTX helpers (all base-sm_80+ features: valid on target sm_103 base)
// ---------------------------------------------------------------------------
static __device__ __forceinline__ uint32_t smem_u32(const void* p) {
    uint32_t a;
    asm("{ .reg .u64 t; cvta.to.shared.u64 t, %1; cvt.u32.u64 %0, t; }"
        : "=r"(a) : "l"(p));
    return a;
}

static __device__ __forceinline__ void mma16816(float* d, const uint32_t* a,
                                                const uint32_t* b) {
    asm volatile(
        "mma.sync.aligned.m16n8k16.row.col.f32.bf16.bf16.f32 "
        "{%0,%1,%2,%3}, {%4,%5,%6,%7}, {%8,%9}, {%0,%1,%2,%3};"
        : "+f"(d[0]), "+f"(d[1]), "+f"(d[2]), "+f"(d[3])
        : "r"(a[0]), "r"(a[1]), "r"(a[2]), "r"(a[3]), "r"(b[0]), "r"(b[1]));
}

static __device__ __forceinline__ void ldsm4(uint32_t* r, uint32_t addr) {
    asm volatile("ldmatrix.sync.aligned.m8n8.x4.shared.b16 {%0,%1,%2,%3}, [%4];"
        : "=r"(r[0]), "=r"(r[1]), "=r"(r[2]), "=r"(r[3]) : "r"(addr));
}

#define CP_ASYNC16(dst, src) \
    asm volatile("cp.async.cg.shared.global [%0], [%1], 16;" \
                 :: "r"(dst), "l"(src))
#define CP_COMMIT() asm volatile("cp.async.commit_group;" ::: "memory")
#define CP_WAIT1()  asm volatile("cp.async.wait_group 1;" ::: "memory")
#define CP_WAIT0()  asm volatile("cp.async.wait_group 0;" ::: "memory")

static __device__ __forceinline__ void split2(float v, __nv_bfloat16& h, __nv_bfloat16& l) {
    h = __float2bfloat16(v);
    l = __float2bfloat16(v - __bfloat162float(h));
}

static __device__ __forceinline__ float gelu_exact(float x) {
    return 0.5f * x * (1.0f + erff(x * 0.70710678118654752f));
}

// ---------------------------------------------------------------------------
// Hop-bias precompute
// ---------------------------------------------------------------------------
__global__ void bias_kernel(const float* __restrict__ Hstack,
                            const float* __restrict__ hop,
                            const float* __restrict__ rel) {
    int h = blockIdx.x;
    float l0 = hop[h*KHOPS+0], l1 = hop[h*KHOPS+1], l2 = hop[h*KHOPS+2], l3 = hop[h*KHOPS+3];
    float m = fmaxf(fmaxf(l0, l1), fmaxf(l2, l3));
    float e0 = expf(l0-m), e1 = expf(l1-m), e2 = expf(l2-m), e3 = expf(l3-m);
    float inv = 1.0f / (e0+e1+e2+e3);
    int ij = threadIdx.x;
    if (ij < NTOK*NTOK) {
        float a = e0*inv*Hstack[0*289+ij] + e1*inv*Hstack[1*289+ij]
                + e2*inv*Hstack[2*289+ij] + e3*inv*Hstack[3*289+ij];
        g_bias[h*289 + ij] = rel[h] * a;
    }
}

// ---------------------------------------------------------------------------
// Weight split fp32 -> (bf16 hi, bf16 lo)
// ---------------------------------------------------------------------------
__global__ void split_kernel(const float* __restrict__ s,
                             __nv_bfloat16* __restrict__ dh,
                             __nv_bfloat16* __restrict__ dl, int n) {
    int i = (blockIdx.x * blockDim.x + threadIdx.x) * 4;
    if (i < n) {
        float4 v = *(const float4*)(s + i);
        __nv_bfloat16 h0, l0, h1, l1, h2, l2, h3, l3;
        split2(v.x, h0, l0); split2(v.y, h1, l1);
        split2(v.z, h2, l2); split2(v.w, h3, l3);
        *(__nv_bfloat162*)(dh + i)     = __halves2bfloat162(h0, h1);
        *(__nv_bfloat162*)(dh + i + 2) = __halves2bfloat162(h2, h3);
        *(__nv_bfloat162*)(dl + i)     = __halves2bfloat162(l0, l1);
        *(__nv_bfloat162*)(dl + i + 2) = __halves2bfloat162(l2, l3);
    }
}

// ---------------------------------------------------------------------------
// LayerNorm -> split bf16 hi/lo. One block per token, 128 threads.
// ---------------------------------------------------------------------------
__global__ void ln_kernel(const float* __restrict__ x,
                          const float* __restrict__ g,
                          const float* __restrict__ b,
                          __nv_bfloat16* __restrict__ oh,
                          __nv_bfloat16* __restrict__ ol) {
    const size_t base = (size_t)blockIdx.x * DIM;
    const int t = threadIdx.x;
    float4 v = *(const float4*)(x + base + t*4);
    float s = v.x + v.y + v.z + v.w;
    float q = v.x*v.x + v.y*v.y + v.z*v.z + v.w*v.w;
    #pragma unroll
    for (int off = 16; off; off >>= 1) {
        s += __shfl_xor_sync(0xffffffffu, s, off);
        q += __shfl_xor_sync(0xffffffffu, q, off);
    }
    __shared__ float sw[4], qw[4];
    int w = t >> 5, l = t & 31;
    if (l == 0) { sw[w] = s; qw[w] = q; }
    __syncthreads();
    float S = sw[0]+sw[1]+sw[2]+sw[3];
    float Q = qw[0]+qw[1]+qw[2]+qw[3];
    float mean = S * (1.0f/512.0f);
    float var  = Q * (1.0f/512.0f) - mean*mean;
    float r = rsqrtf(var + 1e-5f);
    float4 gg = *(const float4*)(g + t*4);
    float4 bb = *(const float4*)(b + t*4);
    float o0 = (v.x-mean)*r*gg.x + bb.x;
    float o1 = (v.y-mean)*r*gg.y + bb.y;
    float o2 = (v.z-mean)*r*gg.z + bb.z;
    float o3 = (v.w-mean)*r*gg.w + bb.w;
    __nv_bfloat16 h0,l0,h1,l1,h2,l2,h3,l3;
    split2(o0,h0,l0); split2(o1,h1,l1); split2(o2,h2,l2); split2(o3,h3,l3);
    *(__nv_bfloat162*)(oh + base + t*4)     = __halves2bfloat162(h0, h1);
    *(__nv_bfloat162*)(oh + base + t*4 + 2) = __halves2bfloat162(h2, h3);
    *(__nv_bfloat162*)(ol + base + t*4)     = __halves2bfloat162(l0, l1);
    *(__nv_bfloat162*)(ol + base + t*4 + 2) = __halves2bfloat162(l2, l3);
}

// ---------------------------------------------------------------------------
// Attention (N=17, hd=64), output split bf16 hi/lo
// ---------------------------------------------------------------------------
__global__ void attn_kernel(const float* __restrict__ qkv,
                            __nv_bfloat16* __restrict__ oh,
                            __nv_bfloat16* __restrict__ ol) {
    const int b = blockIdx.x, h = blockIdx.y;
    __shared__ float  qs[NTOK][64];
    __shared__ float  vs[NTOK][64];
    __shared__ float4 kt4[16][NTOK];
    const int t = threadIdx.x;
    const float* base = qkv + (size_t)b * NTOK * (3*DIM) + h * 64;

    for (int idx = t; idx < NTOK*16; idx += 128) {
        int n = idx >> 4, c = idx & 15;
        const float* p = base + (size_t)n * (3*DIM) + c*4;
        *(float4*)&qs[n][c*4] = *(const float4*)p;
        *(float4*)&vs[n][c*4] = *(const float4*)(p + 2*DIM);
        kt4[c][n]             = *(const float4*)(p + DIM);
    }
    __syncthreads();

    const int warp = t >> 5, lane = t & 31;
    for (int i = warp; i < NTOK; i += 4) {
        float logit = -INFINITY;
        if (lane < NTOK) {
            float s = 0.0f;
            #pragma unroll
            for (int c = 0; c < 16; c++) {
                float4 qv = *(const float4*)&qs[i][c*4];
                float4 kv = kt4[c][lane];
                s += qv.x*kv.x + qv.y*kv.y + qv.z*kv.z + qv.w*kv.w;
            }
            logit = s * 0.125f + g_bias[h*289 + i*NTOK + lane];
        }
        float mx = logit;
        #pragma unroll
        for (int off = 16; off; off >>= 1)
            mx = fmaxf(mx, __shfl_xor_sync(0xffffffffu, mx, off));
        float e = (lane < NTOK) ? __expf(logit - mx) : 0.0f;
        float sum = e;
        #pragma unroll
        for (int off = 16; off; off >>= 1)
            sum += __shfl_xor_sync(0xffffffffu, sum, off);
        float p = e / sum;

        float a0 = 0.0f, a1 = 0.0f;
        #pragma unroll
        for (int j = 0; j < NTOK; j++) {
            float pj = __shfl_sync(0xffffffffu, p, j);
            a0 += pj * vs[j][lane];
            a1 += pj * vs[j][lane + 32];
        }
        size_t o = (size_t)(b*NTOK + i) * DIM + h * 64;
        __nv_bfloat16 hh, ll;
        split2(a0, hh, ll); oh[o + lane]      = hh; ol[o + lane]      = ll;
        split2(a1, hh, ll); oh[o + lane + 32] = hh; ol[o + lane + 32] = ll;
    }
}

// ---------------------------------------------------------------------------
// HMMA split-bf16 GEMM: C[M,N] = A[M,K] @ B[N,K]^T (fp32-class accuracy)
// Tile 128x128xK64, 128 threads (2x2 warps, 64x64 warp tile), 3-stage
// cp.async pipeline, SW128-swizzled smem, ldmatrix fragments, 3 HMMAs per
// accumulator per k16 (AhBh + AhBl + AlBh).
// mode 1: +bias -> fp32 Cf; mode 2: gelu(+bias) -> bf16 Ch/Cl;
// mode 3: +bias+res -> fp32 Cf.
// ---------------------------------------------------------------------------
#define TM 128
#define TN 128
#define TK 64
#define STG 16384                  // bytes per sub-buffer (128 rows x 128B)
#define STAGE_BYTES (4*STG)        // Ah, Al, Bh, Bl
#define NSTAGE 3
#define SMEM_TOTAL (NSTAGE * STAGE_BYTES)   // 196608

static __device__ __forceinline__ void stage_load(
    uint32_t stb,
    const __nv_bfloat16* __restrict__ Ah, const __nv_bfloat16* __restrict__ Al,
    const __nv_bfloat16* __restrict__ Bh, const __nv_bfloat16* __restrict__ Bl,
    int tid, int bm, int bn, int K, int kc)
{
    #pragma unroll
    for (int i = 0; i < 8; i++) {
        int chk = tid + (i << 7);
        int row = chk >> 3, seg = chk & 7;
        uint32_t off = (uint32_t)(row * 128 + seg * 16);
        off ^= (off >> 3) & 0x70;
        size_t ga = (size_t)(bm + row) * K + kc + seg * 8;
        size_t gb = (size_t)(bn + row) * K + kc + seg * 8;
        CP_ASYNC16(stb + off,           Ah + ga);
        CP_ASYNC16(stb + STG + off,     Al + ga);
        CP_ASYNC16(stb + 2*STG + off,   Bh + gb);
        CP_ASYNC16(stb + 3*STG + off,   Bl + gb);
    }
    CP_COMMIT();
}

__global__ __launch_bounds__(128, 1) void gemm_tc(
    const __nv_bfloat16* __restrict__ Ah, const __nv_bfloat16* __restrict__ Al,
    const __nv_bfloat16* __restrict__ Bh, const __nv_bfloat16* __restrict__ Bl,
    const float* __restrict__ bias, const float* __restrict__ res,
    float* __restrict__ Cf,
    __nv_bfloat16* __restrict__ Ch, __nv_bfloat16* __restrict__ Cl,
    int N, int K, int mode)
{
    extern __shared__ __align__(1024) char smem[];
    const uint32_t sb = smem_u32(smem);
    const int tid  = threadIdx.x;
    const int warp = tid >> 5;
    const int lane = tid & 31;
    const int bm = blockIdx.y * TM, bn = blockIdx.x * TN;

    const int wm = (warp & 1) * 64;
    const int wn = (warp >> 1) * 64;

    // ldmatrix per-lane base coordinates
    const int a_row = wm + (lane & 15);
    const int a_ch  = (lane >> 4);                      // 0/1 -> k 16B chunk
    const int b_row = wn + (lane & 7) + ((lane >> 4) << 3);
    const int b_ch  = ((lane >> 3) & 1);

    float acc[4][8][4];
    #pragma unroll
    for (int i = 0; i < 4; i++)
        #pragma unroll
        for (int j = 0; j < 8; j++)
            #pragma unroll
            for (int k = 0; k < 4; k++) acc[i][j][k] = 0.0f;

    const int nch = K >> 6;
    stage_load(sb,               Ah, Al, Bh, Bl, tid, bm, bn, K, 0);
    stage_load(sb + STAGE_BYTES, Ah, Al, Bh, Bl, tid, bm, bn, K, 64);

    for (int c = 0; c < nch; c++) {
        if (c + 1 < nch) { CP_WAIT1(); } else { CP_WAIT0(); }
        __syncthreads();
        if (c + 2 < nch)
            stage_load(sb + ((c + 2) % NSTAGE) * STAGE_BYTES,
                       Ah, Al, Bh, Bl, tid, bm, bn, K, (c + 2) * TK);

        const uint32_t stb = sb + (c % NSTAGE) * STAGE_BYTES;
        #pragma unroll
        for (int kk = 0; kk < 4; kk++) {
            uint32_t ah4[4][4], al4[4][4], bh4[4][4], bl4[4][4];
            #pragma unroll
            for (int mi = 0; mi < 4; mi++) {
                uint32_t off = (uint32_t)((a_row + mi*16) * 128 + (a_ch + kk*2) * 16);
                off ^= (off >> 3) & 0x70;
                ldsm4(ah4[mi], stb + off);
                ldsm4(al4[mi], stb + STG + off);
            }
            #pragma unroll
            for (int nt = 0; nt < 4; nt++) {
                uint32_t off = (uint32_t)((b_row + nt*16) * 128 + (b_ch + kk*2) * 16);
                off ^= (off >> 3) & 0x70;
                ldsm4(bh4[nt], stb + 2*STG + off);
                ldsm4(bl4[nt], stb + 3*STG + off);
            }
            #pragma unroll
            for (int mi = 0; mi < 4; mi++) {
                #pragma unroll
                for (int ni = 0; ni < 8; ni++) {
                    uint32_t* bh = &bh4[ni >> 1][(ni & 1) * 2];
                    uint32_t* bl = &bl4[ni >> 1][(ni & 1) * 2];
                    mma16816(acc[mi][ni], ah4[mi], bh);
                    mma16816(acc[mi][ni], ah4[mi], bl);
                    mma16816(acc[mi][ni], al4[mi], bh);
                }
            }
        }
        __syncthreads();   // all warps done with slot before it is refilled
    }

    // ---------------- epilogue ----------------
    const int er0 = bm + wm + (lane >> 2);
    const int ec0 = bn + wn + (lane & 3) * 2;
    #pragma unroll
    for (int mi = 0; mi < 4; mi++) {
        #pragma unroll
        for (int ni = 0; ni < 8; ni++) {
            const float* a = acc[mi][ni];
            int col  = ec0 + ni * 8;
            int row0 = er0 + mi * 16;
            int row1 = row0 + 8;
            float bv0 = bias[col], bv1 = bias[col + 1];
            float v00 = a[0] + bv0, v01 = a[1] + bv1;
            float v10 = a[2] + bv0, v11 = a[3] + bv1;
            size_t o0 = (size_t)row0 * N + col;
            size_t o1 = (size_t)row1 * N + col;
            if (mode == 2) {
                v00 = gelu_exact(v00); v01 = gelu_exact(v01);
                v10 = gelu_exact(v10); v11 = gelu_exact(v11);
                __nv_bfloat16 h0,l0,h1,l1;
                split2(v00,h0,l0); split2(v01,h1,l1);
                *(__nv_bfloat162*)(Ch + o0) = __halves2bfloat162(h0, h1);
                *(__nv_bfloat162*)(Cl + o0) = __halves2bfloat162(l0, l1);
                split2(v10,h0,l0); split2(v11,h1,l1);
                *(__nv_bfloat162*)(Ch + o1) = __halves2bfloat162(h0, h1);
                *(__nv_bfloat162*)(Cl + o1) = __halves2bfloat162(l0, l1);
            } else if (mode == 3) {
                float2 r0 = *(const float2*)(res + o0);
                float2 r1 = *(const float2*)(res + o1);
                *(float2*)(Cf + o0) = make_float2(v00 + r0.x, v01 + r0.y);
                *(float2*)(Cf + o1) = make_float2(v10 + r1.x, v11 + r1.y);
            } else {
                *(float2*)(Cf + o0) = make_float2(v00, v01);
                *(float2*)(Cf + o1) = make_float2(v10, v11);
            }
        }
    }
}

// ---------------------------------------------------------------------------
// kernel_launch
// ---------------------------------------------------------------------------
extern "C" void kernel_launch(void* const* d_in, const int* in_sizes, int n_in,
                              void* d_out, int out_size) {
    const float* x      = (const float*)d_in[0];
    const float* Hstack = (const float*)d_in[1];
    const float* hop    = (const float*)d_in[2];
    const float* rel    = (const float*)d_in[3];
    const float* qkv_w  = (const float*)d_in[4];
    const float* qkv_b  = (const float*)d_in[5];
    const float* proj_w = (const float*)d_in[6];
    const float* proj_b = (const float*)d_in[7];
    const float* ln1_g  = (const float*)d_in[8];
    const float* ln1_b  = (const float*)d_in[9];
    const float* ln2_g  = (const float*)d_in[10];
    const float* ln2_b  = (const float*)d_in[11];
    const float* fc1_w  = (const float*)d_in[12];
    const float* fc1_b  = (const float*)d_in[13];
    const float* fc2_w  = (const float*)d_in[14];
    const float* fc2_b  = (const float*)d_in[15];
    float* out = (float*)d_out;

    float *big;
    __nv_bfloat16 *ah, *al, *bh, *bl, *wh, *wl;
    cudaGetSymbolAddress((void**)&big, g_big);
    cudaGetSymbolAddress((void**)&ah,  g_ah);
    cudaGetSymbolAddress((void**)&al,  g_al);
    cudaGetSymbolAddress((void**)&bh,  g_bh);
    cudaGetSymbolAddress((void**)&bl,  g_bl);
    cudaGetSymbolAddress((void**)&wh,  g_wh);
    cudaGetSymbolAddress((void**)&wl,  g_wl);

    cudaFuncSetAttribute(gemm_tc, cudaFuncAttributeMaxDynamicSharedMemorySize,
                         SMEM_TOTAL);

    cudaMemcpyAsync(out, x, (size_t)MTOT * DIM * sizeof(float),
                    cudaMemcpyDeviceToDevice, 0);

    bias_kernel<<<HEADS, NTOK * NTOK>>>(Hstack, hop, rel);

    // one-time weight splits
    split_kernel<<<(4*WQKV_PER/4 + 255)/256, 256>>>(qkv_w,  wh + WQKV_OFF,  wl + WQKV_OFF,  4*WQKV_PER);
    split_kernel<<<(4*WPROJ_PER/4 + 255)/256, 256>>>(proj_w, wh + WPROJ_OFF, wl + WPROJ_OFF, 4*WPROJ_PER);
    split_kernel<<<(4*WFC1_PER/4 + 255)/256, 256>>>(fc1_w,  wh + WFC1_OFF,  wl + WFC1_OFF,  4*WFC1_PER);
    split_kernel<<<(4*WFC2_PER/4 + 255)/256, 256>>>(fc2_w,  wh + WFC2_OFF,  wl + WFC2_OFF,  4*WFC2_PER);

    for (int d = 0; d < DEPTH; d++) {
        // LN1 -> (ah, al)
        ln_kernel<<<MTOT, 128>>>(out, ln1_g + d*DIM, ln1_b + d*DIM, ah, al);
        // qkv = h @ qkv_w.T + b -> big (fp32)
        gemm_tc<<<dim3(3*DIM/TN, MTOT/TM), 128, SMEM_TOTAL>>>(
            ah, al, wh + WQKV_OFF + (size_t)d*WQKV_PER, wl + WQKV_OFF + (size_t)d*WQKV_PER,
            qkv_b + (size_t)d*3*DIM, nullptr, big, nullptr, nullptr, 3*DIM, DIM, 1);
        // attention -> (ah, al)
        attn_kernel<<<dim3(BATCH, HEADS), 128>>>(big, ah, al);
        // x += attn @ proj_w.T + b
        gemm_tc<<<dim3(DIM/TN, MTOT/TM), 128, SMEM_TOTAL>>>(
            ah, al, wh + WPROJ_OFF + (size_t)d*WPROJ_PER, wl + WPROJ_OFF + (size_t)d*WPROJ_PER,
            proj_b + (size_t)d*DIM, out, out, nullptr, nullptr, DIM, DIM, 3);
        // LN2 -> (ah, al)
        ln_kernel<<<MTOT, 128>>>(out, ln2_g + d*DIM, ln2_b + d*DIM, ah, al);
        // h2 = gelu(h @ fc1_w.T + b) -> (bh, bl)
        gemm_tc<<<dim3(HIDDEN/TN, MTOT/TM), 128, SMEM_TOTAL>>>(
            ah, al, wh + WFC1_OFF + (size_t)d*WFC1_PER, wl + WFC1_OFF + (size_t)d*WFC1_PER,
            fc1_b + (size_t)d*HIDDEN, nullptr, nullptr, bh, bl, HIDDEN, DIM, 2);
        // x += h2 @ fc2_w.T + b
        gemm_tc<<<dim3(DIM/TN, MTOT/TM), 128, SMEM_TOTAL>>>(
            bh, bl, wh + WFC2_OFF + (size_t)d*WFC2_PER, wl + WFC2_OFF + (size_t)d*WFC2_PER,
            fc2_b + (size_t)d*DIM, out, out, nullptr, nullptr, DIM, HIDDEN, 3);
    }
}

// round 8
// speedup vs baseline: 2.1928x; 1.0002x over previous
#include <cuda_runtime.h>
#include <cuda_bf16.h>
#include <math.h>
#include <stdint.h>

// ---------------------------------------------------------------------------
// Problem constants
// ---------------------------------------------------------------------------
#define DEPTH   4
#define HEADS   8
#define DIM     512
#define HIDDEN  1024
#define NTOK    17
#define BATCH   2048
#define MTOT    (BATCH * NTOK)          // 34816 tokens (272 * 128)
#define KHOPS   4

// weight-split buffer offsets (elements)
#define WQKV_PER  (3*DIM*DIM)
#define WQKV_OFF  0
#define WPROJ_PER (DIM*DIM)
#define WPROJ_OFF (4*WQKV_PER)
#define WFC1_PER  (HIDDEN*DIM)
#define WFC1_OFF  (WPROJ_OFF + 4*WPROJ_PER)
#define WFC2_PER  (DIM*HIDDEN)
#define WFC2_OFF  (WFC1_OFF + 4*WFC1_PER)
#define WTOT      (WFC2_OFF + 4*WFC2_PER)

// ---------------------------------------------------------------------------
// Scratch (device globals)
// ---------------------------------------------------------------------------
__device__ float         g_big [(size_t)MTOT * 3 * DIM];   // qkv fp32
__device__ __nv_bfloat16 g_ah  [(size_t)MTOT * DIM];       // activation hi
__device__ __nv_bfloat16 g_al  [(size_t)MTOT * DIM];       // activation lo
__device__ __nv_bfloat16 g_bh  [(size_t)MTOT * HIDDEN];    // mlp hidden hi
__device__ __nv_bfloat16 g_bl  [(size_t)MTOT * HIDDEN];    // mlp hidden lo
__device__ __nv_bfloat16 g_wh  [WTOT];                     // weights hi
__device__ __nv_bfloat16 g_wl  [WTOT];                     // weights lo
__device__ float         g_bias[HEADS * NTOK * NTOK];      // hop bias

// ---------------------------------------------------------------------------
// PTX helpers (all base-sm_80+ features: valid on target sm_103 base)
// ---------------------------------------------------------------------------
static __device__ __forceinline__ uint32_t smem_u32(const void* p) {
    uint32_t a;
    asm("{ .reg .u64 t; cvta.to.shared.u64 t, %1; cvt.u32.u64 %0, t; }"
        : "=r"(a) : "l"(p));
    return a;
}

static __device__ __forceinline__ void mma16816(float* d, const uint32_t* a,
                                                const uint32_t* b) {
    asm volatile(
        "mma.sync.aligned.m16n8k16.row.col.f32.bf16.bf16.f32 "
        "{%0,%1,%2,%3}, {%4,%5,%6,%7}, {%8,%9}, {%0,%1,%2,%3};"
        : "+f"(d[0]), "+f"(d[1]), "+f"(d[2]), "+f"(d[3])
        : "r"(a[0]), "r"(a[1]), "r"(a[2]), "r"(a[3]), "r"(b[0]), "r"(b[1]));
}

static __device__ __forceinline__ void ldsm4(uint32_t* r, uint32_t addr) {
    asm volatile("ldmatrix.sync.aligned.m8n8.x4.shared.b16 {%0,%1,%2,%3}, [%4];"
        : "=r"(r[0]), "=r"(r[1]), "=r"(r[2]), "=r"(r[3]) : "r"(addr));
}

#define CP_ASYNC16(dst, src) \
    asm volatile("cp.async.cg.shared.global [%0], [%1], 16;" \
                 :: "r"(dst), "l"(src))
#define CP_COMMIT() asm volatile("cp.async.commit_group;" ::: "memory")
#define CP_WAIT1()  asm volatile("cp.async.wait_group 1;" ::: "memory")
#define CP_WAIT0()  asm volatile("cp.async.wait_group 0;" ::: "memory")

static __device__ __forceinline__ void split2(float v, __nv_bfloat16& h, __nv_bfloat16& l) {
    h = __float2bfloat16(v);
    l = __float2bfloat16(v - __bfloat162float(h));
}

static __device__ __forceinline__ float gelu_exact(float x) {
    return 0.5f * x * (1.0f + erff(x * 0.70710678118654752f));
}

// ---------------------------------------------------------------------------
// Hop-bias precompute
// ---------------------------------------------------------------------------
__global__ void bias_kernel(const float* __restrict__ Hstack,
                            const float* __restrict__ hop,
                            const float* __restrict__ rel) {
    int h = blockIdx.x;
    float l0 = hop[h*KHOPS+0], l1 = hop[h*KHOPS+1], l2 = hop[h*KHOPS+2], l3 = hop[h*KHOPS+3];
    float m = fmaxf(fmaxf(l0, l1), fmaxf(l2, l3));
    float e0 = expf(l0-m), e1 = expf(l1-m), e2 = expf(l2-m), e3 = expf(l3-m);
    float inv = 1.0f / (e0+e1+e2+e3);
    int ij = threadIdx.x;
    if (ij < NTOK*NTOK) {
        float a = e0*inv*Hstack[0*289+ij] + e1*inv*Hstack[1*289+ij]
                + e2*inv*Hstack[2*289+ij] + e3*inv*Hstack[3*289+ij];
        g_bias[h*289 + ij] = rel[h] * a;
    }
}

// ---------------------------------------------------------------------------
// Weight split fp32 -> (bf16 hi, bf16 lo)
// ---------------------------------------------------------------------------
__global__ void split_kernel(const float* __restrict__ s,
                             __nv_bfloat16* __restrict__ dh,
                             __nv_bfloat16* __restrict__ dl, int n) {
    int i = (blockIdx.x * blockDim.x + threadIdx.x) * 4;
    if (i < n) {
        float4 v = *(const float4*)(s + i);
        __nv_bfloat16 h0, l0, h1, l1, h2, l2, h3, l3;
        split2(v.x, h0, l0); split2(v.y, h1, l1);
        split2(v.z, h2, l2); split2(v.w, h3, l3);
        *(__nv_bfloat162*)(dh + i)     = __halves2bfloat162(h0, h1);
        *(__nv_bfloat162*)(dh + i + 2) = __halves2bfloat162(h2, h3);
        *(__nv_bfloat162*)(dl + i)     = __halves2bfloat162(l0, l1);
        *(__nv_bfloat162*)(dl + i + 2) = __halves2bfloat162(l2, l3);
    }
}

// ---------------------------------------------------------------------------
// LayerNorm -> split bf16 hi/lo. One block per token, 128 threads.
// ---------------------------------------------------------------------------
__global__ void ln_kernel(const float* __restrict__ x,
                          const float* __restrict__ g,
                          const float* __restrict__ b,
                          __nv_bfloat16* __restrict__ oh,
                          __nv_bfloat16* __restrict__ ol) {
    const size_t base = (size_t)blockIdx.x * DIM;
    const int t = threadIdx.x;
    float4 v = *(const float4*)(x + base + t*4);
    float s = v.x + v.y + v.z + v.w;
    float q = v.x*v.x + v.y*v.y + v.z*v.z + v.w*v.w;
    #pragma unroll
    for (int off = 16; off; off >>= 1) {
        s += __shfl_xor_sync(0xffffffffu, s, off);
        q += __shfl_xor_sync(0xffffffffu, q, off);
    }
    __shared__ float sw[4], qw[4];
    int w = t >> 5, l = t & 31;
    if (l == 0) { sw[w] = s; qw[w] = q; }
    __syncthreads();
    float S = sw[0]+sw[1]+sw[2]+sw[3];
    float Q = qw[0]+qw[1]+qw[2]+qw[3];
    float mean = S * (1.0f/512.0f);
    float var  = Q * (1.0f/512.0f) - mean*mean;
    float r = rsqrtf(var + 1e-5f);
    float4 gg = *(const float4*)(g + t*4);
    float4 bb = *(const float4*)(b + t*4);
    float o0 = (v.x-mean)*r*gg.x + bb.x;
    float o1 = (v.y-mean)*r*gg.y + bb.y;
    float o2 = (v.z-mean)*r*gg.z + bb.z;
    float o3 = (v.w-mean)*r*gg.w + bb.w;
    __nv_bfloat16 h0,l0,h1,l1,h2,l2,h3,l3;
    split2(o0,h0,l0); split2(o1,h1,l1); split2(o2,h2,l2); split2(o3,h3,l3);
    *(__nv_bfloat162*)(oh + base + t*4)     = __halves2bfloat162(h0, h1);
    *(__nv_bfloat162*)(oh + base + t*4 + 2) = __halves2bfloat162(h2, h3);
    *(__nv_bfloat162*)(ol + base + t*4)     = __halves2bfloat162(l0, l1);
    *(__nv_bfloat162*)(ol + base + t*4 + 2) = __halves2bfloat162(l2, l3);
}

// ---------------------------------------------------------------------------
// Attention (N=17, hd=64), output split bf16 hi/lo
// ---------------------------------------------------------------------------
__global__ void attn_kernel(const float* __restrict__ qkv,
                            __nv_bfloat16* __restrict__ oh,
                            __nv_bfloat16* __restrict__ ol) {
    const int b = blockIdx.x, h = blockIdx.y;
    __shared__ float  qs[NTOK][64];
    __shared__ float  vs[NTOK][64];
    __shared__ float4 kt4[16][NTOK];
    const int t = threadIdx.x;
    const float* base = qkv + (size_t)b * NTOK * (3*DIM) + h * 64;

    for (int idx = t; idx < NTOK*16; idx += 128) {
        int n = idx >> 4, c = idx & 15;
        const float* p = base + (size_t)n * (3*DIM) + c*4;
        *(float4*)&qs[n][c*4] = *(const float4*)p;
        *(float4*)&vs[n][c*4] = *(const float4*)(p + 2*DIM);
        kt4[c][n]             = *(const float4*)(p + DIM);
    }
    __syncthreads();

    const int warp = t >> 5, lane = t & 31;
    for (int i = warp; i < NTOK; i += 4) {
        float logit = -INFINITY;
        if (lane < NTOK) {
            float s = 0.0f;
            #pragma unroll
            for (int c = 0; c < 16; c++) {
                float4 qv = *(const float4*)&qs[i][c*4];
                float4 kv = kt4[c][lane];
                s += qv.x*kv.x + qv.y*kv.y + qv.z*kv.z + qv.w*kv.w;
            }
            logit = s * 0.125f + g_bias[h*289 + i*NTOK + lane];
        }
        float mx = logit;
        #pragma unroll
        for (int off = 16; off; off >>= 1)
            mx = fmaxf(mx, __shfl_xor_sync(0xffffffffu, mx, off));
        float e = (lane < NTOK) ? __expf(logit - mx) : 0.0f;
        float sum = e;
        #pragma unroll
        for (int off = 16; off; off >>= 1)
            sum += __shfl_xor_sync(0xffffffffu, sum, off);
        float p = e / sum;

        float a0 = 0.0f, a1 = 0.0f;
        #pragma unroll
        for (int j = 0; j < NTOK; j++) {
            float pj = __shfl_sync(0xffffffffu, p, j);
            a0 += pj * vs[j][lane];
            a1 += pj * vs[j][lane + 32];
        }
        size_t o = (size_t)(b*NTOK + i) * DIM + h * 64;
        __nv_bfloat16 hh, ll;
        split2(a0, hh, ll); oh[o + lane]      = hh; ol[o + lane]      = ll;
        split2(a1, hh, ll); oh[o + lane + 32] = hh; ol[o + lane + 32] = ll;
    }
}

// ---------------------------------------------------------------------------
// HMMA split-bf16 GEMM: C[M,N] = A[M,K] @ B[N,K]^T (fp32-class accuracy)
// Tile 128x128xK64, 128 threads (2x2 warps, 64x64 warp tile), 3-stage
// cp.async pipeline, SW128-swizzled smem, ldmatrix fragments, 3 HMMAs per
// accumulator per k16 (AhBh + AhBl + AlBh).
// mode 1: +bias -> fp32 Cf; mode 2: gelu(+bias) -> bf16 Ch/Cl;
// mode 3: +bias+res -> fp32 Cf.
// ---------------------------------------------------------------------------
#define TM 128
#define TN 128
#define TK 64
#define STG 16384                  // bytes per sub-buffer (128 rows x 128B)
#define STAGE_BYTES (4*STG)        // Ah, Al, Bh, Bl
#define NSTAGE 3
#define SMEM_TOTAL (NSTAGE * STAGE_BYTES)   // 196608

static __device__ __forceinline__ void stage_load(
    uint32_t stb,
    const __nv_bfloat16* __restrict__ Ah, const __nv_bfloat16* __restrict__ Al,
    const __nv_bfloat16* __restrict__ Bh, const __nv_bfloat16* __restrict__ Bl,
    int tid, int bm, int bn, int K, int kc)
{
    #pragma unroll
    for (int i = 0; i < 8; i++) {
        int chk = tid + (i << 7);
        int row = chk >> 3, seg = chk & 7;
        uint32_t off = (uint32_t)(row * 128 + seg * 16);
        off ^= (off >> 3) & 0x70;
        size_t ga = (size_t)(bm + row) * K + kc + seg * 8;
        size_t gb = (size_t)(bn + row) * K + kc + seg * 8;
        CP_ASYNC16(stb + off,           Ah + ga);
        CP_ASYNC16(stb + STG + off,     Al + ga);
        CP_ASYNC16(stb + 2*STG + off,   Bh + gb);
        CP_ASYNC16(stb + 3*STG + off,   Bl + gb);
    }
    CP_COMMIT();
}

__global__ __launch_bounds__(128, 1) void gemm_tc(
    const __nv_bfloat16* __restrict__ Ah, const __nv_bfloat16* __restrict__ Al,
    const __nv_bfloat16* __restrict__ Bh, const __nv_bfloat16* __restrict__ Bl,
    const float* __restrict__ bias, const float* __restrict__ res,
    float* __restrict__ Cf,
    __nv_bfloat16* __restrict__ Ch, __nv_bfloat16* __restrict__ Cl,
    int N, int K, int mode)
{
    extern __shared__ __align__(1024) char smem[];
    const uint32_t sb = smem_u32(smem);
    const int tid  = threadIdx.x;
    const int warp = tid >> 5;
    const int lane = tid & 31;
    const int bm = blockIdx.y * TM, bn = blockIdx.x * TN;

    const int wm = (warp & 1) * 64;
    const int wn = (warp >> 1) * 64;

    // ldmatrix per-lane base coordinates
    const int a_row = wm + (lane & 15);
    const int a_ch  = (lane >> 4);                      // 0/1 -> k 16B chunk
    const int b_row = wn + (lane & 7) + ((lane >> 4) << 3);
    const int b_ch  = ((lane >> 3) & 1);

    float acc[4][8][4];
    #pragma unroll
    for (int i = 0; i < 4; i++)
        #pragma unroll
        for (int j = 0; j < 8; j++)
            #pragma unroll
            for (int k = 0; k < 4; k++) acc[i][j][k] = 0.0f;

    const int nch = K >> 6;
    stage_load(sb,               Ah, Al, Bh, Bl, tid, bm, bn, K, 0);
    stage_load(sb + STAGE_BYTES, Ah, Al, Bh, Bl, tid, bm, bn, K, 64);

    for (int c = 0; c < nch; c++) {
        if (c + 1 < nch) { CP_WAIT1(); } else { CP_WAIT0(); }
        __syncthreads();
        if (c + 2 < nch)
            stage_load(sb + ((c + 2) % NSTAGE) * STAGE_BYTES,
                       Ah, Al, Bh, Bl, tid, bm, bn, K, (c + 2) * TK);

        const uint32_t stb = sb + (c % NSTAGE) * STAGE_BYTES;
        #pragma unroll
        for (int kk = 0; kk < 4; kk++) {
            uint32_t ah4[4][4], al4[4][4], bh4[4][4], bl4[4][4];
            #pragma unroll
            for (int mi = 0; mi < 4; mi++) {
                uint32_t off = (uint32_t)((a_row + mi*16) * 128 + (a_ch + kk*2) * 16);
                off ^= (off >> 3) & 0x70;
                ldsm4(ah4[mi], stb + off);
                ldsm4(al4[mi], stb + STG + off);
            }
            #pragma unroll
            for (int nt = 0; nt < 4; nt++) {
                uint32_t off = (uint32_t)((b_row + nt*16) * 128 + (b_ch + kk*2) * 16);
                off ^= (off >> 3) & 0x70;
                ldsm4(bh4[nt], stb + 2*STG + off);
                ldsm4(bl4[nt], stb + 3*STG + off);
            }
            #pragma unroll
            for (int mi = 0; mi < 4; mi++) {
                #pragma unroll
                for (int ni = 0; ni < 8; ni++) {
                    uint32_t* bh = &bh4[ni >> 1][(ni & 1) * 2];
                    uint32_t* bl = &bl4[ni >> 1][(ni & 1) * 2];
                    mma16816(acc[mi][ni], ah4[mi], bh);
                    mma16816(acc[mi][ni], ah4[mi], bl);
                    mma16816(acc[mi][ni], al4[mi], bh);
                }
            }
        }
        __syncthreads();   // all warps done with slot before it is refilled
    }

    // ---------------- epilogue ----------------
    const int er0 = bm + wm + (lane >> 2);
    const int ec0 = bn + wn + (lane & 3) * 2;
    #pragma unroll
    for (int mi = 0; mi < 4; mi++) {
        #pragma unroll
        for (int ni = 0; ni < 8; ni++) {
            const float* a = acc[mi][ni];
            int col  = ec0 + ni * 8;
            int row0 = er0 + mi * 16;
            int row1 = row0 + 8;
            float bv0 = bias[col], bv1 = bias[col + 1];
            float v00 = a[0] + bv0, v01 = a[1] + bv1;
            float v10 = a[2] + bv0, v11 = a[3] + bv1;
            size_t o0 = (size_t)row0 * N + col;
            size_t o1 = (size_t)row1 * N + col;
            if (mode == 2) {
                v00 = gelu_exact(v00); v01 = gelu_exact(v01);
                v10 = gelu_exact(v10); v11 = gelu_exact(v11);
                __nv_bfloat16 h0,l0,h1,l1;
                split2(v00,h0,l0); split2(v01,h1,l1);
                *(__nv_bfloat162*)(Ch + o0) = __halves2bfloat162(h0, h1);
                *(__nv_bfloat162*)(Cl + o0) = __halves2bfloat162(l0, l1);
                split2(v10,h0,l0); split2(v11,h1,l1);
                *(__nv_bfloat162*)(Ch + o1) = __halves2bfloat162(h0, h1);
                *(__nv_bfloat162*)(Cl + o1) = __halves2bfloat162(l0, l1);
            } else if (mode == 3) {
                float2 r0 = *(const float2*)(res + o0);
                float2 r1 = *(const float2*)(res + o1);
                *(float2*)(Cf + o0) = make_float2(v00 + r0.x, v01 + r0.y);
                *(float2*)(Cf + o1) = make_float2(v10 + r1.x, v11 + r1.y);
            } else {
                *(float2*)(Cf + o0) = make_float2(v00, v01);
                *(float2*)(Cf + o1) = make_float2(v10, v11);
            }
        }
    }
}

// ---------------------------------------------------------------------------
// kernel_launch
// ---------------------------------------------------------------------------
extern "C" void kernel_launch(void* const* d_in, const int* in_sizes, int n_in,
                              void* d_out, int out_size) {
    const float* x      = (const float*)d_in[0];
    const float* Hstack = (const float*)d_in[1];
    const float* hop    = (const float*)d_in[2];
    const float* rel    = (const float*)d_in[3];
    const float* qkv_w  = (const float*)d_in[4];
    const float* qkv_b  = (const float*)d_in[5];
    const float* proj_w = (const float*)d_in[6];
    const float* proj_b = (const float*)d_in[7];
    const float* ln1_g  = (const float*)d_in[8];
    const float* ln1_b  = (const float*)d_in[9];
    const float* ln2_g  = (const float*)d_in[10];
    const float* ln2_b  = (const float*)d_in[11];
    const float* fc1_w  = (const float*)d_in[12];
    const float* fc1_b  = (const float*)d_in[13];
    const float* fc2_w  = (const float*)d_in[14];
    const float* fc2_b  = (const float*)d_in[15];
    float* out = (float*)d_out;

    float *big;
    __nv_bfloat16 *ah, *al, *bh, *bl, *wh, *wl;
    cudaGetSymbolAddress((void**)&big, g_big);
    cudaGetSymbolAddress((void**)&ah,  g_ah);
    cudaGetSymbolAddress((void**)&al,  g_al);
    cudaGetSymbolAddress((void**)&bh,  g_bh);
    cudaGetSymbolAddress((void**)&bl,  g_bl);
    cudaGetSymbolAddress((void**)&wh,  g_wh);
    cudaGetSymbolAddress((void**)&wl,  g_wl);

    cudaFuncSetAttribute(gemm_tc, cudaFuncAttributeMaxDynamicSharedMemorySize,
                         SMEM_TOTAL);

    cudaMemcpyAsync(out, x, (size_t)MTOT * DIM * sizeof(float),
                    cudaMemcpyDeviceToDevice, 0);

    bias_kernel<<<HEADS, NTOK * NTOK>>>(Hstack, hop, rel);

    // one-time weight splits
    split_kernel<<<(4*WQKV_PER/4 + 255)/256, 256>>>(qkv_w,  wh + WQKV_OFF,  wl + WQKV_OFF,  4*WQKV_PER);
    split_kernel<<<(4*WPROJ_PER/4 + 255)/256, 256>>>(proj_w, wh + WPROJ_OFF, wl + WPROJ_OFF, 4*WPROJ_PER);
    split_kernel<<<(4*WFC1_PER/4 + 255)/256, 256>>>(fc1_w,  wh + WFC1_OFF,  wl + WFC1_OFF,  4*WFC1_PER);
    split_kernel<<<(4*WFC2_PER/4 + 255)/256, 256>>>(fc2_w,  wh + WFC2_OFF,  wl + WFC2_OFF,  4*WFC2_PER);

    for (int d = 0; d < DEPTH; d++) {
        // LN1 -> (ah, al)
        ln_kernel<<<MTOT, 128>>>(out, ln1_g + d*DIM, ln1_b + d*DIM, ah, al);
        // qkv = h @ qkv_w.T + b -> big (fp32)
        gemm_tc<<<dim3(3*DIM/TN, MTOT/TM), 128, SMEM_TOTAL>>>(
            ah, al, wh + WQKV_OFF + (size_t)d*WQKV_PER, wl + WQKV_OFF + (size_t)d*WQKV_PER,
            qkv_b + (size_t)d*3*DIM, nullptr, big, nullptr, nullptr, 3*DIM, DIM, 1);
        // attention -> (ah, al)
        attn_kernel<<<dim3(BATCH, HEADS), 128>>>(big, ah, al);
        // x += attn @ proj_w.T + b
        gemm_tc<<<dim3(DIM/TN, MTOT/TM), 128, SMEM_TOTAL>>>(
            ah, al, wh + WPROJ_OFF + (size_t)d*WPROJ_PER, wl + WPROJ_OFF + (size_t)d*WPROJ_PER,
            proj_b + (size_t)d*DIM, out, out, nullptr, nullptr, DIM, DIM, 3);
        // LN2 -> (ah, al)
        ln_kernel<<<MTOT, 128>>>(out, ln2_g + d*DIM, ln2_b + d*DIM, ah, al);
        // h2 = gelu(h @ fc1_w.T + b) -> (bh, bl)
        gemm_tc<<<dim3(HIDDEN/TN, MTOT/TM), 128, SMEM_TOTAL>>>(
            ah, al, wh + WFC1_OFF + (size_t)d*WFC1_PER, wl + WFC1_OFF + (size_t)d*WFC1_PER,
            fc1_b + (size_t)d*HIDDEN, nullptr, nullptr, bh, bl, HIDDEN, DIM, 2);
        // x += h2 @ fc2_w.T + b
        gemm_tc<<<dim3(DIM/TN, MTOT/TM), 128, SMEM_TOTAL>>>(
            bh, bl, wh + WFC2_OFF + (size_t)d*WFC2_PER, wl + WFC2_OFF + (size_t)d*WFC2_PER,
            fc2_b + (size_t)d*DIM, out, out, nullptr, nullptr, DIM, HIDDEN, 3);
    }
}

// round 9
// speedup vs baseline: 2.1933x; 1.0002x over previous
#include <cuda_runtime.h>
#include <cuda_bf16.h>
#include <math.h>
#include <stdint.h>

// ---------------------------------------------------------------------------
// Problem constants
// ---------------------------------------------------------------------------
#define DEPTH   4
#define HEADS   8
#define DIM     512
#define HIDDEN  1024
#define NTOK    17
#define BATCH   2048
#define MTOT    (BATCH * NTOK)          // 34816 tokens (272 * 128)
#define KHOPS   4

// weight-split buffer offsets (elements)
#define WQKV_PER  (3*DIM*DIM)
#define WQKV_OFF  0
#define WPROJ_PER (DIM*DIM)
#define WPROJ_OFF (4*WQKV_PER)
#define WFC1_PER  (HIDDEN*DIM)
#define WFC1_OFF  (WPROJ_OFF + 4*WPROJ_PER)
#define WFC2_PER  (DIM*HIDDEN)
#define WFC2_OFF  (WFC1_OFF + 4*WFC1_PER)
#define WTOT      (WFC2_OFF + 4*WFC2_PER)

// ---------------------------------------------------------------------------
// Scratch (device globals)
// ---------------------------------------------------------------------------
__device__ float         g_big [(size_t)MTOT * 3 * DIM];   // qkv fp32
__device__ __nv_bfloat16 g_ah  [(size_t)MTOT * DIM];       // activation hi
__device__ __nv_bfloat16 g_al  [(size_t)MTOT * DIM];       // activation lo
__device__ __nv_bfloat16 g_bh  [(size_t)MTOT * HIDDEN];    // mlp hidden hi
__device__ __nv_bfloat16 g_bl  [(size_t)MTOT * HIDDEN];    // mlp hidden lo
__device__ __nv_bfloat16 g_wh  [WTOT];                     // weights hi
__device__ __nv_bfloat16 g_wl  [WTOT];                     // weights lo
__device__ float         g_bias[HEADS * NTOK * NTOK];      // hop bias

// ---------------------------------------------------------------------------
// PTX helpers (all base-sm_80+ features: valid on target sm_103 base)
// ---------------------------------------------------------------------------
static __device__ __forceinline__ uint32_t smem_u32(const void* p) {
    uint32_t a;
    asm("{ .reg .u64 t; cvta.to.shared.u64 t, %1; cvt.u32.u64 %0, t; }"
        : "=r"(a) : "l"(p));
    return a;
}

static __device__ __forceinline__ void mma16816(float* d, const uint32_t* a,
                                                const uint32_t* b) {
    asm volatile(
        "mma.sync.aligned.m16n8k16.row.col.f32.bf16.bf16.f32 "
        "{%0,%1,%2,%3}, {%4,%5,%6,%7}, {%8,%9}, {%0,%1,%2,%3};"
        : "+f"(d[0]), "+f"(d[1]), "+f"(d[2]), "+f"(d[3])
        : "r"(a[0]), "r"(a[1]), "r"(a[2]), "r"(a[3]), "r"(b[0]), "r"(b[1]));
}

static __device__ __forceinline__ void ldsm4(uint32_t* r, uint32_t addr) {
    asm volatile("ldmatrix.sync.aligned.m8n8.x4.shared.b16 {%0,%1,%2,%3}, [%4];"
        : "=r"(r[0]), "=r"(r[1]), "=r"(r[2]), "=r"(r[3]) : "r"(addr));
}

#define CP_ASYNC16(dst, src) \
    asm volatile("cp.async.cg.shared.global [%0], [%1], 16;" \
                 :: "r"(dst), "l"(src))
#define CP_COMMIT() asm volatile("cp.async.commit_group;" ::: "memory")
#define CP_WAIT1()  asm volatile("cp.async.wait_group 1;" ::: "memory")
#define CP_WAIT0()  asm volatile("cp.async.wait_group 0;" ::: "memory")

static __device__ __forceinline__ void split2(float v, __nv_bfloat16& h, __nv_bfloat16& l) {
    h = __float2bfloat16(v);
    l = __float2bfloat16(v - __bfloat162float(h));
}

static __device__ __forceinline__ float gelu_exact(float x) {
    return 0.5f * x * (1.0f + erff(x * 0.70710678118654752f));
}

// ---------------------------------------------------------------------------
// Hop-bias precompute
// ---------------------------------------------------------------------------
__global__ void bias_kernel(const float* __restrict__ Hstack,
                            const float* __restrict__ hop,
                            const float* __restrict__ rel) {
    int h = blockIdx.x;
    float l0 = hop[h*KHOPS+0], l1 = hop[h*KHOPS+1], l2 = hop[h*KHOPS+2], l3 = hop[h*KHOPS+3];
    float m = fmaxf(fmaxf(l0, l1), fmaxf(l2, l3));
    float e0 = expf(l0-m), e1 = expf(l1-m), e2 = expf(l2-m), e3 = expf(l3-m);
    float inv = 1.0f / (e0+e1+e2+e3);
    int ij = threadIdx.x;
    if (ij < NTOK*NTOK) {
        float a = e0*inv*Hstack[0*289+ij] + e1*inv*Hstack[1*289+ij]
                + e2*inv*Hstack[2*289+ij] + e3*inv*Hstack[3*289+ij];
        g_bias[h*289 + ij] = rel[h] * a;
    }
}

// ---------------------------------------------------------------------------
// Weight split fp32 -> (bf16 hi, bf16 lo)
// ---------------------------------------------------------------------------
__global__ void split_kernel(const float* __restrict__ s,
                             __nv_bfloat16* __restrict__ dh,
                             __nv_bfloat16* __restrict__ dl, int n) {
    int i = (blockIdx.x * blockDim.x + threadIdx.x) * 4;
    if (i < n) {
        float4 v = *(const float4*)(s + i);
        __nv_bfloat16 h0, l0, h1, l1, h2, l2, h3, l3;
        split2(v.x, h0, l0); split2(v.y, h1, l1);
        split2(v.z, h2, l2); split2(v.w, h3, l3);
        *(__nv_bfloat162*)(dh + i)     = __halves2bfloat162(h0, h1);
        *(__nv_bfloat162*)(dh + i + 2) = __halves2bfloat162(h2, h3);
        *(__nv_bfloat162*)(dl + i)     = __halves2bfloat162(l0, l1);
        *(__nv_bfloat162*)(dl + i + 2) = __halves2bfloat162(l2, l3);
    }
}

// ---------------------------------------------------------------------------
// LayerNorm -> split bf16 hi/lo. One block per token, 128 threads.
// ---------------------------------------------------------------------------
__global__ void ln_kernel(const float* __restrict__ x,
                          const float* __restrict__ g,
                          const float* __restrict__ b,
                          __nv_bfloat16* __restrict__ oh,
                          __nv_bfloat16* __restrict__ ol) {
    const size_t base = (size_t)blockIdx.x * DIM;
    const int t = threadIdx.x;
    float4 v = *(const float4*)(x + base + t*4);
    float s = v.x + v.y + v.z + v.w;
    float q = v.x*v.x + v.y*v.y + v.z*v.z + v.w*v.w;
    #pragma unroll
    for (int off = 16; off; off >>= 1) {
        s += __shfl_xor_sync(0xffffffffu, s, off);
        q += __shfl_xor_sync(0xffffffffu, q, off);
    }
    __shared__ float sw[4], qw[4];
    int w = t >> 5, l = t & 31;
    if (l == 0) { sw[w] = s; qw[w] = q; }
    __syncthreads();
    float S = sw[0]+sw[1]+sw[2]+sw[3];
    float Q = qw[0]+qw[1]+qw[2]+qw[3];
    float mean = S * (1.0f/512.0f);
    float var  = Q * (1.0f/512.0f) - mean*mean;
    float r = rsqrtf(var + 1e-5f);
    float4 gg = *(const float4*)(g + t*4);
    float4 bb = *(const float4*)(b + t*4);
    float o0 = (v.x-mean)*r*gg.x + bb.x;
    float o1 = (v.y-mean)*r*gg.y + bb.y;
    float o2 = (v.z-mean)*r*gg.z + bb.z;
    float o3 = (v.w-mean)*r*gg.w + bb.w;
    __nv_bfloat16 h0,l0,h1,l1,h2,l2,h3,l3;
    split2(o0,h0,l0); split2(o1,h1,l1); split2(o2,h2,l2); split2(o3,h3,l3);
    *(__nv_bfloat162*)(oh + base + t*4)     = __halves2bfloat162(h0, h1);
    *(__nv_bfloat162*)(oh + base + t*4 + 2) = __halves2bfloat162(h2, h3);
    *(__nv_bfloat162*)(ol + base + t*4)     = __halves2bfloat162(l0, l1);
    *(__nv_bfloat162*)(ol + base + t*4 + 2) = __halves2bfloat162(l2, l3);
}

// ---------------------------------------------------------------------------
// Attention (N=17, hd=64), output split bf16 hi/lo
// ---------------------------------------------------------------------------
__global__ void attn_kernel(const float* __restrict__ qkv,
                            __nv_bfloat16* __restrict__ oh,
                            __nv_bfloat16* __restrict__ ol) {
    const int b = blockIdx.x, h = blockIdx.y;
    __shared__ float  qs[NTOK][64];
    __shared__ float  vs[NTOK][64];
    __shared__ float4 kt4[16][NTOK];
    const int t = threadIdx.x;
    const float* base = qkv + (size_t)b * NTOK * (3*DIM) + h * 64;

    for (int idx = t; idx < NTOK*16; idx += 128) {
        int n = idx >> 4, c = idx & 15;
        const float* p = base + (size_t)n * (3*DIM) + c*4;
        *(float4*)&qs[n][c*4] = *(const float4*)p;
        *(float4*)&vs[n][c*4] = *(const float4*)(p + 2*DIM);
        kt4[c][n]             = *(const float4*)(p + DIM);
    }
    __syncthreads();

    const int warp = t >> 5, lane = t & 31;
    for (int i = warp; i < NTOK; i += 4) {
        float logit = -INFINITY;
        if (lane < NTOK) {
            float s = 0.0f;
            #pragma unroll
            for (int c = 0; c < 16; c++) {
                float4 qv = *(const float4*)&qs[i][c*4];
                float4 kv = kt4[c][lane];
                s += qv.x*kv.x + qv.y*kv.y + qv.z*kv.z + qv.w*kv.w;
            }
            logit = s * 0.125f + g_bias[h*289 + i*NTOK + lane];
        }
        float mx = logit;
        #pragma unroll
        for (int off = 16; off; off >>= 1)
            mx = fmaxf(mx, __shfl_xor_sync(0xffffffffu, mx, off));
        float e = (lane < NTOK) ? __expf(logit - mx) : 0.0f;
        float sum = e;
        #pragma unroll
        for (int off = 16; off; off >>= 1)
            sum += __shfl_xor_sync(0xffffffffu, sum, off);
        float p = e / sum;

        float a0 = 0.0f, a1 = 0.0f;
        #pragma unroll
        for (int j = 0; j < NTOK; j++) {
            float pj = __shfl_sync(0xffffffffu, p, j);
            a0 += pj * vs[j][lane];
            a1 += pj * vs[j][lane + 32];
        }
        size_t o = (size_t)(b*NTOK + i) * DIM + h * 64;
        __nv_bfloat16 hh, ll;
        split2(a0, hh, ll); oh[o + lane]      = hh; ol[o + lane]      = ll;
        split2(a1, hh, ll); oh[o + lane + 32] = hh; ol[o + lane + 32] = ll;
    }
}

// ---------------------------------------------------------------------------
// HMMA split-bf16 GEMM: C[M,N] = A[M,K] @ B[N,K]^T (fp32-class accuracy)
// Tile 128x128xK64, 128 threads (2x2 warps, 64x64 warp tile), 3-stage
// cp.async pipeline, SW128-swizzled smem, ldmatrix fragments, 3 HMMAs per
// accumulator per k16 (AhBh + AhBl + AlBh).
// mode 1: +bias -> fp32 Cf; mode 2: gelu(+bias) -> bf16 Ch/Cl;
// mode 3: +bias+res -> fp32 Cf.
// ---------------------------------------------------------------------------
#define TM 128
#define TN 128
#define TK 64
#define STG 16384                  // bytes per sub-buffer (128 rows x 128B)
#define STAGE_BYTES (4*STG)        // Ah, Al, Bh, Bl
#define NSTAGE 3
#define SMEM_TOTAL (NSTAGE * STAGE_BYTES)   // 196608

static __device__ __forceinline__ void stage_load(
    uint32_t stb,
    const __nv_bfloat16* __restrict__ Ah, const __nv_bfloat16* __restrict__ Al,
    const __nv_bfloat16* __restrict__ Bh, const __nv_bfloat16* __restrict__ Bl,
    int tid, int bm, int bn, int K, int kc)
{
    #pragma unroll
    for (int i = 0; i < 8; i++) {
        int chk = tid + (i << 7);
        int row = chk >> 3, seg = chk & 7;
        uint32_t off = (uint32_t)(row * 128 + seg * 16);
        off ^= (off >> 3) & 0x70;
        size_t ga = (size_t)(bm + row) * K + kc + seg * 8;
        size_t gb = (size_t)(bn + row) * K + kc + seg * 8;
        CP_ASYNC16(stb + off,           Ah + ga);
        CP_ASYNC16(stb + STG + off,     Al + ga);
        CP_ASYNC16(stb + 2*STG + off,   Bh + gb);
        CP_ASYNC16(stb + 3*STG + off,   Bl + gb);
    }
    CP_COMMIT();
}

__global__ __launch_bounds__(128, 1) void gemm_tc(
    const __nv_bfloat16* __restrict__ Ah, const __nv_bfloat16* __restrict__ Al,
    const __nv_bfloat16* __restrict__ Bh, const __nv_bfloat16* __restrict__ Bl,
    const float* __restrict__ bias, const float* __restrict__ res,
    float* __restrict__ Cf,
    __nv_bfloat16* __restrict__ Ch, __nv_bfloat16* __restrict__ Cl,
    int N, int K, int mode)
{
    extern __shared__ __align__(1024) char smem[];
    const uint32_t sb = smem_u32(smem);
    const int tid  = threadIdx.x;
    const int warp = tid >> 5;
    const int lane = tid & 31;
    const int bm = blockIdx.y * TM, bn = blockIdx.x * TN;

    const int wm = (warp & 1) * 64;
    const int wn = (warp >> 1) * 64;

    // ldmatrix per-lane base coordinates
    const int a_row = wm + (lane & 15);
    const int a_ch  = (lane >> 4);                      // 0/1 -> k 16B chunk
    const int b_row = wn + (lane & 7) + ((lane >> 4) << 3);
    const int b_ch  = ((lane >> 3) & 1);

    float acc[4][8][4];
    #pragma unroll
    for (int i = 0; i < 4; i++)
        #pragma unroll
        for (int j = 0; j < 8; j++)
            #pragma unroll
            for (int k = 0; k < 4; k++) acc[i][j][k] = 0.0f;

    const int nch = K >> 6;
    stage_load(sb,               Ah, Al, Bh, Bl, tid, bm, bn, K, 0);
    stage_load(sb + STAGE_BYTES, Ah, Al, Bh, Bl, tid, bm, bn, K, 64);

    for (int c = 0; c < nch; c++) {
        if (c + 1 < nch) { CP_WAIT1(); } else { CP_WAIT0(); }
        __syncthreads();
        if (c + 2 < nch)
            stage_load(sb + ((c + 2) % NSTAGE) * STAGE_BYTES,
                       Ah, Al, Bh, Bl, tid, bm, bn, K, (c + 2) * TK);

        const uint32_t stb = sb + (c % NSTAGE) * STAGE_BYTES;
        #pragma unroll
        for (int kk = 0; kk < 4; kk++) {
            uint32_t ah4[4][4], al4[4][4], bh4[4][4], bl4[4][4];
            #pragma unroll
            for (int mi = 0; mi < 4; mi++) {
                uint32_t off = (uint32_t)((a_row + mi*16) * 128 + (a_ch + kk*2) * 16);
                off ^= (off >> 3) & 0x70;
                ldsm4(ah4[mi], stb + off);
                ldsm4(al4[mi], stb + STG + off);
            }
            #pragma unroll
            for (int nt = 0; nt < 4; nt++) {
                uint32_t off = (uint32_t)((b_row + nt*16) * 128 + (b_ch + kk*2) * 16);
                off ^= (off >> 3) & 0x70;
                ldsm4(bh4[nt], stb + 2*STG + off);
                ldsm4(bl4[nt], stb + 3*STG + off);
            }
            #pragma unroll
            for (int mi = 0; mi < 4; mi++) {
                #pragma unroll
                for (int ni = 0; ni < 8; ni++) {
                    uint32_t* bh = &bh4[ni >> 1][(ni & 1) * 2];
                    uint32_t* bl = &bl4[ni >> 1][(ni & 1) * 2];
                    mma16816(acc[mi][ni], ah4[mi], bh);
                    mma16816(acc[mi][ni], ah4[mi], bl);
                    mma16816(acc[mi][ni], al4[mi], bh);
                }
            }
        }
        __syncthreads();   // all warps done with slot before it is refilled
    }

    // ---------------- epilogue ----------------
    const int er0 = bm + wm + (lane >> 2);
    const int ec0 = bn + wn + (lane & 3) * 2;
    #pragma unroll
    for (int mi = 0; mi < 4; mi++) {
        #pragma unroll
        for (int ni = 0; ni < 8; ni++) {
            const float* a = acc[mi][ni];
            int col  = ec0 + ni * 8;
            int row0 = er0 + mi * 16;
            int row1 = row0 + 8;
            float bv0 = bias[col], bv1 = bias[col + 1];
            float v00 = a[0] + bv0, v01 = a[1] + bv1;
            float v10 = a[2] + bv0, v11 = a[3] + bv1;
            size_t o0 = (size_t)row0 * N + col;
            size_t o1 = (size_t)row1 * N + col;
            if (mode == 2) {
                v00 = gelu_exact(v00); v01 = gelu_exact(v01);
                v10 = gelu_exact(v10); v11 = gelu_exact(v11);
                __nv_bfloat16 h0,l0,h1,l1;
                split2(v00,h0,l0); split2(v01,h1,l1);
                *(__nv_bfloat162*)(Ch + o0) = __halves2bfloat162(h0, h1);
                *(__nv_bfloat162*)(Cl + o0) = __halves2bfloat162(l0, l1);
                split2(v10,h0,l0); split2(v11,h1,l1);
                *(__nv_bfloat162*)(Ch + o1) = __halves2bfloat162(h0, h1);
                *(__nv_bfloat162*)(Cl + o1) = __halves2bfloat162(l0, l1);
            } else if (mode == 3) {
                float2 r0 = *(const float2*)(res + o0);
                float2 r1 = *(const float2*)(res + o1);
                *(float2*)(Cf + o0) = make_float2(v00 + r0.x, v01 + r0.y);
                *(float2*)(Cf + o1) = make_float2(v10 + r1.x, v11 + r1.y);
            } else {
                *(float2*)(Cf + o0) = make_float2(v00, v01);
                *(float2*)(Cf + o1) = make_float2(v10, v11);
            }
        }
    }
}

// ---------------------------------------------------------------------------
// kernel_launch
// ---------------------------------------------------------------------------
extern "C" void kernel_launch(void* const* d_in, const int* in_sizes, int n_in,
                              void* d_out, int out_size) {
    const float* x      = (const float*)d_in[0];
    const float* Hstack = (const float*)d_in[1];
    const float* hop    = (const float*)d_in[2];
    const float* rel    = (const float*)d_in[3];
    const float* qkv_w  = (const float*)d_in[4];
    const float* qkv_b  = (const float*)d_in[5];
    const float* proj_w = (const float*)d_in[6];
    const float* proj_b = (const float*)d_in[7];
    const float* ln1_g  = (const float*)d_in[8];
    const float* ln1_b  = (const float*)d_in[9];
    const float* ln2_g  = (const float*)d_in[10];
    const float* ln2_b  = (const float*)d_in[11];
    const float* fc1_w  = (const float*)d_in[12];
    const float* fc1_b  = (const float*)d_in[13];
    const float* fc2_w  = (const float*)d_in[14];
    const float* fc2_b  = (const float*)d_in[15];
    float* out = (float*)d_out;

    float *big;
    __nv_bfloat16 *ah, *al, *bh, *bl, *wh, *wl;
    cudaGetSymbolAddress((void**)&big, g_big);
    cudaGetSymbolAddress((void**)&ah,  g_ah);
    cudaGetSymbolAddress((void**)&al,  g_al);
    cudaGetSymbolAddress((void**)&bh,  g_bh);
    cudaGetSymbolAddress((void**)&bl,  g_bl);
    cudaGetSymbolAddress((void**)&wh,  g_wh);
    cudaGetSymbolAddress((void**)&wl,  g_wl);

    cudaFuncSetAttribute(gemm_tc, cudaFuncAttributeMaxDynamicSharedMemorySize,
                         SMEM_TOTAL);

    cudaMemcpyAsync(out, x, (size_t)MTOT * DIM * sizeof(float),
                    cudaMemcpyDeviceToDevice, 0);

    bias_kernel<<<HEADS, NTOK * NTOK>>>(Hstack, hop, rel);

    // one-time weight splits
    split_kernel<<<(4*WQKV_PER/4 + 255)/256, 256>>>(qkv_w,  wh + WQKV_OFF,  wl + WQKV_OFF,  4*WQKV_PER);
    split_kernel<<<(4*WPROJ_PER/4 + 255)/256, 256>>>(proj_w, wh + WPROJ_OFF, wl + WPROJ_OFF, 4*WPROJ_PER);
    split_kernel<<<(4*WFC1_PER/4 + 255)/256, 256>>>(fc1_w,  wh + WFC1_OFF,  wl + WFC1_OFF,  4*WFC1_PER);
    split_kernel<<<(4*WFC2_PER/4 + 255)/256, 256>>>(fc2_w,  wh + WFC2_OFF,  wl + WFC2_OFF,  4*WFC2_PER);

    for (int d = 0; d < DEPTH; d++) {
        // LN1 -> (ah, al)
        ln_kernel<<<MTOT, 128>>>(out, ln1_g + d*DIM, ln1_b + d*DIM, ah, al);
        // qkv = h @ qkv_w.T + b -> big (fp32)
        gemm_tc<<<dim3(3*DIM/TN, MTOT/TM), 128, SMEM_TOTAL>>>(
            ah, al, wh + WQKV_OFF + (size_t)d*WQKV_PER, wl + WQKV_OFF + (size_t)d*WQKV_PER,
            qkv_b + (size_t)d*3*DIM, nullptr, big, nullptr, nullptr, 3*DIM, DIM, 1);
        // attention -> (ah, al)
        attn_kernel<<<dim3(BATCH, HEADS), 128>>>(big, ah, al);
        // x += attn @ proj_w.T + b
        gemm_tc<<<dim3(DIM/TN, MTOT/TM), 128, SMEM_TOTAL>>>(
            ah, al, wh + WPROJ_OFF + (size_t)d*WPROJ_PER, wl + WPROJ_OFF + (size_t)d*WPROJ_PER,
            proj_b + (size_t)d*DIM, out, out, nullptr, nullptr, DIM, DIM, 3);
        // LN2 -> (ah, al)
        ln_kernel<<<MTOT, 128>>>(out, ln2_g + d*DIM, ln2_b + d*DIM, ah, al);
        // h2 = gelu(h @ fc1_w.T + b) -> (bh, bl)
        gemm_tc<<<dim3(HIDDEN/TN, MTOT/TM), 128, SMEM_TOTAL>>>(
            ah, al, wh + WFC1_OFF + (size_t)d*WFC1_PER, wl + WFC1_OFF + (size_t)d*WFC1_PER,
            fc1_b + (size_t)d*HIDDEN, nullptr, nullptr, bh, bl, HIDDEN, DIM, 2);
        // x += h2 @ fc2_w.T + b
        gemm_tc<<<dim3(DIM/TN, MTOT/TM), 128, SMEM_TOTAL>>>(
            bh, bl, wh + WFC2_OFF + (size_t)d*WFC2_PER, wl + WFC2_OFF + (size_t)d*WFC2_PER,
            fc2_b + (size_t)d*DIM, out, out, nullptr, nullptr, DIM, HIDDEN, 3);
    }
}

// round 10
// speedup vs baseline: 2.1956x; 1.0011x over previous
#include <cuda_runtime.h>
#include <cuda_bf16.h>
#include <math.h>
#include <stdint.h>

// ---------------------------------------------------------------------------
// Problem constants
// ---------------------------------------------------------------------------
#define DEPTH   4
#define HEADS   8
#define DIM     512
#define HIDDEN  1024
#define NTOK    17
#define BATCH   2048
#define MTOT    (BATCH * NTOK)          // 34816 tokens (272 * 128)
#define KHOPS   4

// weight-split buffer offsets (elements)
#define WQKV_PER  (3*DIM*DIM)
#define WQKV_OFF  0
#define WPROJ_PER (DIM*DIM)
#define WPROJ_OFF (4*WQKV_PER)
#define WFC1_PER  (HIDDEN*DIM)
#define WFC1_OFF  (WPROJ_OFF + 4*WPROJ_PER)
#define WFC2_PER  (DIM*HIDDEN)
#define WFC2_OFF  (WFC1_OFF + 4*WFC1_PER)
#define WTOT      (WFC2_OFF + 4*WFC2_PER)

// ---------------------------------------------------------------------------
// Scratch (device globals)
// ---------------------------------------------------------------------------
__device__ float         g_big [(size_t)MTOT * 3 * DIM];   // qkv fp32
__device__ __nv_bfloat16 g_ah  [(size_t)MTOT * DIM];       // activation hi
__device__ __nv_bfloat16 g_al  [(size_t)MTOT * DIM];       // activation lo
__device__ __nv_bfloat16 g_bh  [(size_t)MTOT * HIDDEN];    // mlp hidden hi
__device__ __nv_bfloat16 g_bl  [(size_t)MTOT * HIDDEN];    // mlp hidden lo
__device__ __nv_bfloat16 g_wh  [WTOT];                     // weights hi
__device__ __nv_bfloat16 g_wl  [WTOT];                     // weights lo
__device__ float         g_bias[HEADS * NTOK * NTOK];      // hop bias

// ---------------------------------------------------------------------------
// PTX helpers (all base-sm_80+ features: valid on target sm_103 base)
// ---------------------------------------------------------------------------
static __device__ __forceinline__ uint32_t smem_u32(const void* p) {
    uint32_t a;
    asm("{ .reg .u64 t; cvta.to.shared.u64 t, %1; cvt.u32.u64 %0, t; }"
        : "=r"(a) : "l"(p));
    return a;
}

static __device__ __forceinline__ void mma16816(float* d, const uint32_t* a,
                                                const uint32_t* b) {
    asm volatile(
        "mma.sync.aligned.m16n8k16.row.col.f32.bf16.bf16.f32 "
        "{%0,%1,%2,%3}, {%4,%5,%6,%7}, {%8,%9}, {%0,%1,%2,%3};"
        : "+f"(d[0]), "+f"(d[1]), "+f"(d[2]), "+f"(d[3])
        : "r"(a[0]), "r"(a[1]), "r"(a[2]), "r"(a[3]), "r"(b[0]), "r"(b[1]));
}

static __device__ __forceinline__ void ldsm4(uint32_t* r, uint32_t addr) {
    asm volatile("ldmatrix.sync.aligned.m8n8.x4.shared.b16 {%0,%1,%2,%3}, [%4];"
        : "=r"(r[0]), "=r"(r[1]), "=r"(r[2]), "=r"(r[3]) : "r"(addr));
}

#define CP_ASYNC16(dst, src) \
    asm volatile("cp.async.cg.shared.global [%0], [%1], 16;" \
                 :: "r"(dst), "l"(src))
#define CP_COMMIT() asm volatile("cp.async.commit_group;" ::: "memory")
#define CP_WAIT1()  asm volatile("cp.async.wait_group 1;" ::: "memory")
#define CP_WAIT0()  asm volatile("cp.async.wait_group 0;" ::: "memory")

static __device__ __forceinline__ void split2(float v, __nv_bfloat16& h, __nv_bfloat16& l) {
    h = __float2bfloat16(v);
    l = __float2bfloat16(v - __bfloat162float(h));
}

static __device__ __forceinline__ float gelu_exact(float x) {
    return 0.5f * x * (1.0f + erff(x * 0.70710678118654752f));
}

// ---------------------------------------------------------------------------
// Hop-bias precompute
// ---------------------------------------------------------------------------
__global__ void bias_kernel(const float* __restrict__ Hstack,
                            const float* __restrict__ hop,
                            const float* __restrict__ rel) {
    int h = blockIdx.x;
    float l0 = hop[h*KHOPS+0], l1 = hop[h*KHOPS+1], l2 = hop[h*KHOPS+2], l3 = hop[h*KHOPS+3];
    float m = fmaxf(fmaxf(l0, l1), fmaxf(l2, l3));
    float e0 = expf(l0-m), e1 = expf(l1-m), e2 = expf(l2-m), e3 = expf(l3-m);
    float inv = 1.0f / (e0+e1+e2+e3);
    int ij = threadIdx.x;
    if (ij < NTOK*NTOK) {
        float a = e0*inv*Hstack[0*289+ij] + e1*inv*Hstack[1*289+ij]
                + e2*inv*Hstack[2*289+ij] + e3*inv*Hstack[3*289+ij];
        g_bias[h*289 + ij] = rel[h] * a;
    }
}

// ---------------------------------------------------------------------------
// Weight split fp32 -> (bf16 hi, bf16 lo)
// ---------------------------------------------------------------------------
__global__ void split_kernel(const float* __restrict__ s,
                             __nv_bfloat16* __restrict__ dh,
                             __nv_bfloat16* __restrict__ dl, int n) {
    int i = (blockIdx.x * blockDim.x + threadIdx.x) * 4;
    if (i < n) {
        float4 v = *(const float4*)(s + i);
        __nv_bfloat16 h0, l0, h1, l1, h2, l2, h3, l3;
        split2(v.x, h0, l0); split2(v.y, h1, l1);
        split2(v.z, h2, l2); split2(v.w, h3, l3);
        *(__nv_bfloat162*)(dh + i)     = __halves2bfloat162(h0, h1);
        *(__nv_bfloat162*)(dh + i + 2) = __halves2bfloat162(h2, h3);
        *(__nv_bfloat162*)(dl + i)     = __halves2bfloat162(l0, l1);
        *(__nv_bfloat162*)(dl + i + 2) = __halves2bfloat162(l2, l3);
    }
}

// ---------------------------------------------------------------------------
// LayerNorm -> split bf16 hi/lo. One block per token, 128 threads.
// ---------------------------------------------------------------------------
__global__ void ln_kernel(const float* __restrict__ x,
                          const float* __restrict__ g,
                          const float* __restrict__ b,
                          __nv_bfloat16* __restrict__ oh,
                          __nv_bfloat16* __restrict__ ol) {
    const size_t base = (size_t)blockIdx.x * DIM;
    const int t = threadIdx.x;
    float4 v = *(const float4*)(x + base + t*4);
    float s = v.x + v.y + v.z + v.w;
    float q = v.x*v.x + v.y*v.y + v.z*v.z + v.w*v.w;
    #pragma unroll
    for (int off = 16; off; off >>= 1) {
        s += __shfl_xor_sync(0xffffffffu, s, off);
        q += __shfl_xor_sync(0xffffffffu, q, off);
    }
    __shared__ float sw[4], qw[4];
    int w = t >> 5, l = t & 31;
    if (l == 0) { sw[w] = s; qw[w] = q; }
    __syncthreads();
    float S = sw[0]+sw[1]+sw[2]+sw[3];
    float Q = qw[0]+qw[1]+qw[2]+qw[3];
    float mean = S * (1.0f/512.0f);
    float var  = Q * (1.0f/512.0f) - mean*mean;
    float r = rsqrtf(var + 1e-5f);
    float4 gg = *(const float4*)(g + t*4);
    float4 bb = *(const float4*)(b + t*4);
    float o0 = (v.x-mean)*r*gg.x + bb.x;
    float o1 = (v.y-mean)*r*gg.y + bb.y;
    float o2 = (v.z-mean)*r*gg.z + bb.z;
    float o3 = (v.w-mean)*r*gg.w + bb.w;
    __nv_bfloat16 h0,l0,h1,l1,h2,l2,h3,l3;
    split2(o0,h0,l0); split2(o1,h1,l1); split2(o2,h2,l2); split2(o3,h3,l3);
    *(__nv_bfloat162*)(oh + base + t*4)     = __halves2bfloat162(h0, h1);
    *(__nv_bfloat162*)(oh + base + t*4 + 2) = __halves2bfloat162(h2, h3);
    *(__nv_bfloat162*)(ol + base + t*4)     = __halves2bfloat162(l0, l1);
    *(__nv_bfloat162*)(ol + base + t*4 + 2) = __halves2bfloat162(l2, l3);
}

// ---------------------------------------------------------------------------
// Attention (N=17, hd=64), output split bf16 hi/lo
// ---------------------------------------------------------------------------
__global__ void attn_kernel(const float* __restrict__ qkv,
                            __nv_bfloat16* __restrict__ oh,
                            __nv_bfloat16* __restrict__ ol) {
    const int b = blockIdx.x, h = blockIdx.y;
    __shared__ float  qs[NTOK][64];
    __shared__ float  vs[NTOK][64];
    __shared__ float4 kt4[16][NTOK];
    const int t = threadIdx.x;
    const float* base = qkv + (size_t)b * NTOK * (3*DIM) + h * 64;

    for (int idx = t; idx < NTOK*16; idx += 128) {
        int n = idx >> 4, c = idx & 15;
        const float* p = base + (size_t)n * (3*DIM) + c*4;
        *(float4*)&qs[n][c*4] = *(const float4*)p;
        *(float4*)&vs[n][c*4] = *(const float4*)(p + 2*DIM);
        kt4[c][n]             = *(const float4*)(p + DIM);
    }
    __syncthreads();

    const int warp = t >> 5, lane = t & 31;
    for (int i = warp; i < NTOK; i += 4) {
        float logit = -INFINITY;
        if (lane < NTOK) {
            float s = 0.0f;
            #pragma unroll
            for (int c = 0; c < 16; c++) {
                float4 qv = *(const float4*)&qs[i][c*4];
                float4 kv = kt4[c][lane];
                s += qv.x*kv.x + qv.y*kv.y + qv.z*kv.z + qv.w*kv.w;
            }
            logit = s * 0.125f + g_bias[h*289 + i*NTOK + lane];
        }
        float mx = logit;
        #pragma unroll
        for (int off = 16; off; off >>= 1)
            mx = fmaxf(mx, __shfl_xor_sync(0xffffffffu, mx, off));
        float e = (lane < NTOK) ? __expf(logit - mx) : 0.0f;
        float sum = e;
        #pragma unroll
        for (int off = 16; off; off >>= 1)
            sum += __shfl_xor_sync(0xffffffffu, sum, off);
        float p = e / sum;

        float a0 = 0.0f, a1 = 0.0f;
        #pragma unroll
        for (int j = 0; j < NTOK; j++) {
            float pj = __shfl_sync(0xffffffffu, p, j);
            a0 += pj * vs[j][lane];
            a1 += pj * vs[j][lane + 32];
        }
        size_t o = (size_t)(b*NTOK + i) * DIM + h * 64;
        __nv_bfloat16 hh, ll;
        split2(a0, hh, ll); oh[o + lane]      = hh; ol[o + lane]      = ll;
        split2(a1, hh, ll); oh[o + lane + 32] = hh; ol[o + lane + 32] = ll;
    }
}

// ---------------------------------------------------------------------------
// HMMA split-bf16 GEMM: C[M,N] = A[M,K] @ B[N,K]^T (fp32-class accuracy)
// Tile 128x128xK64, 128 threads (2x2 warps, 64x64 warp tile), 3-stage
// cp.async pipeline, SW128-swizzled smem, ldmatrix fragments, 3 HMMAs per
// accumulator per k16 (AhBh + AhBl + AlBh).
// mode 1: +bias -> fp32 Cf; mode 2: gelu(+bias) -> bf16 Ch/Cl;
// mode 3: +bias+res -> fp32 Cf.
// ---------------------------------------------------------------------------
#define TM 128
#define TN 128
#define TK 64
#define STG 16384                  // bytes per sub-buffer (128 rows x 128B)
#define STAGE_BYTES (4*STG)        // Ah, Al, Bh, Bl
#define NSTAGE 3
#define SMEM_TOTAL (NSTAGE * STAGE_BYTES)   // 196608

static __device__ __forceinline__ void stage_load(
    uint32_t stb,
    const __nv_bfloat16* __restrict__ Ah, const __nv_bfloat16* __restrict__ Al,
    const __nv_bfloat16* __restrict__ Bh, const __nv_bfloat16* __restrict__ Bl,
    int tid, int bm, int bn, int K, int kc)
{
    #pragma unroll
    for (int i = 0; i < 8; i++) {
        int chk = tid + (i << 7);
        int row = chk >> 3, seg = chk & 7;
        uint32_t off = (uint32_t)(row * 128 + seg * 16);
        off ^= (off >> 3) & 0x70;
        size_t ga = (size_t)(bm + row) * K + kc + seg * 8;
        size_t gb = (size_t)(bn + row) * K + kc + seg * 8;
        CP_ASYNC16(stb + off,           Ah + ga);
        CP_ASYNC16(stb + STG + off,     Al + ga);
        CP_ASYNC16(stb + 2*STG + off,   Bh + gb);
        CP_ASYNC16(stb + 3*STG + off,   Bl + gb);
    }
    CP_COMMIT();
}

__global__ __launch_bounds__(128, 1) void gemm_tc(
    const __nv_bfloat16* __restrict__ Ah, const __nv_bfloat16* __restrict__ Al,
    const __nv_bfloat16* __restrict__ Bh, const __nv_bfloat16* __restrict__ Bl,
    const float* __restrict__ bias, const float* __restrict__ res,
    float* __restrict__ Cf,
    __nv_bfloat16* __restrict__ Ch, __nv_bfloat16* __restrict__ Cl,
    int N, int K, int mode)
{
    extern __shared__ __align__(1024) char smem[];
    const uint32_t sb = smem_u32(smem);
    const int tid  = threadIdx.x;
    const int warp = tid >> 5;
    const int lane = tid & 31;
    const int bm = blockIdx.y * TM, bn = blockIdx.x * TN;

    const int wm = (warp & 1) * 64;
    const int wn = (warp >> 1) * 64;

    // ldmatrix per-lane base coordinates
    const int a_row = wm + (lane & 15);
    const int a_ch  = (lane >> 4);                      // 0/1 -> k 16B chunk
    const int b_row = wn + (lane & 7) + ((lane >> 4) << 3);
    const int b_ch  = ((lane >> 3) & 1);

    float acc[4][8][4];
    #pragma unroll
    for (int i = 0; i < 4; i++)
        #pragma unroll
        for (int j = 0; j < 8; j++)
            #pragma unroll
            for (int k = 0; k < 4; k++) acc[i][j][k] = 0.0f;

    const int nch = K >> 6;
    stage_load(sb,               Ah, Al, Bh, Bl, tid, bm, bn, K, 0);
    stage_load(sb + STAGE_BYTES, Ah, Al, Bh, Bl, tid, bm, bn, K, 64);

    for (int c = 0; c < nch; c++) {
        if (c + 1 < nch) { CP_WAIT1(); } else { CP_WAIT0(); }
        __syncthreads();
        if (c + 2 < nch)
            stage_load(sb + ((c + 2) % NSTAGE) * STAGE_BYTES,
                       Ah, Al, Bh, Bl, tid, bm, bn, K, (c + 2) * TK);

        const uint32_t stb = sb + (c % NSTAGE) * STAGE_BYTES;
        #pragma unroll
        for (int kk = 0; kk < 4; kk++) {
            uint32_t ah4[4][4], al4[4][4], bh4[4][4], bl4[4][4];
            #pragma unroll
            for (int mi = 0; mi < 4; mi++) {
                uint32_t off = (uint32_t)((a_row + mi*16) * 128 + (a_ch + kk*2) * 16);
                off ^= (off >> 3) & 0x70;
                ldsm4(ah4[mi], stb + off);
                ldsm4(al4[mi], stb + STG + off);
            }
            #pragma unroll
            for (int nt = 0; nt < 4; nt++) {
                uint32_t off = (uint32_t)((b_row + nt*16) * 128 + (b_ch + kk*2) * 16);
                off ^= (off >> 3) & 0x70;
                ldsm4(bh4[nt], stb + 2*STG + off);
                ldsm4(bl4[nt], stb + 3*STG + off);
            }
            #pragma unroll
            for (int mi = 0; mi < 4; mi++) {
                #pragma unroll
                for (int ni = 0; ni < 8; ni++) {
                    uint32_t* bh = &bh4[ni >> 1][(ni & 1) * 2];
                    uint32_t* bl = &bl4[ni >> 1][(ni & 1) * 2];
                    mma16816(acc[mi][ni], ah4[mi], bh);
                    mma16816(acc[mi][ni], ah4[mi], bl);
                    mma16816(acc[mi][ni], al4[mi], bh);
                }
            }
        }
        __syncthreads();   // all warps done with slot before it is refilled
    }

    // ---------------- epilogue ----------------
    const int er0 = bm + wm + (lane >> 2);
    const int ec0 = bn + wn + (lane & 3) * 2;
    #pragma unroll
    for (int mi = 0; mi < 4; mi++) {
        #pragma unroll
        for (int ni = 0; ni < 8; ni++) {
            const float* a = acc[mi][ni];
            int col  = ec0 + ni * 8;
            int row0 = er0 + mi * 16;
            int row1 = row0 + 8;
            float bv0 = bias[col], bv1 = bias[col + 1];
            float v00 = a[0] + bv0, v01 = a[1] + bv1;
            float v10 = a[2] + bv0, v11 = a[3] + bv1;
            size_t o0 = (size_t)row0 * N + col;
            size_t o1 = (size_t)row1 * N + col;
            if (mode == 2) {
                v00 = gelu_exact(v00); v01 = gelu_exact(v01);
                v10 = gelu_exact(v10); v11 = gelu_exact(v11);
                __nv_bfloat16 h0,l0,h1,l1;
                split2(v00,h0,l0); split2(v01,h1,l1);
                *(__nv_bfloat162*)(Ch + o0) = __halves2bfloat162(h0, h1);
                *(__nv_bfloat162*)(Cl + o0) = __halves2bfloat162(l0, l1);
                split2(v10,h0,l0); split2(v11,h1,l1);
                *(__nv_bfloat162*)(Ch + o1) = __halves2bfloat162(h0, h1);
                *(__nv_bfloat162*)(Cl + o1) = __halves2bfloat162(l0, l1);
            } else if (mode == 3) {
                float2 r0 = *(const float2*)(res + o0);
                float2 r1 = *(const float2*)(res + o1);
                *(float2*)(Cf + o0) = make_float2(v00 + r0.x, v01 + r0.y);
                *(float2*)(Cf + o1) = make_float2(v10 + r1.x, v11 + r1.y);
            } else {
                *(float2*)(Cf + o0) = make_float2(v00, v01);
                *(float2*)(Cf + o1) = make_float2(v10, v11);
            }
        }
    }
}

// ---------------------------------------------------------------------------
// kernel_launch
// ---------------------------------------------------------------------------
extern "C" void kernel_launch(void* const* d_in, const int* in_sizes, int n_in,
                              void* d_out, int out_size) {
    const float* x      = (const float*)d_in[0];
    const float* Hstack = (const float*)d_in[1];
    const float* hop    = (const float*)d_in[2];
    const float* rel    = (const float*)d_in[3];
    const float* qkv_w  = (const float*)d_in[4];
    const float* qkv_b  = (const float*)d_in[5];
    const float* proj_w = (const float*)d_in[6];
    const float* proj_b = (const float*)d_in[7];
    const float* ln1_g  = (const float*)d_in[8];
    const float* ln1_b  = (const float*)d_in[9];
    const float* ln2_g  = (const float*)d_in[10];
    const float* ln2_b  = (const float*)d_in[11];
    const float* fc1_w  = (const float*)d_in[12];
    const float* fc1_b  = (const float*)d_in[13];
    const float* fc2_w  = (const float*)d_in[14];
    const float* fc2_b  = (const float*)d_in[15];
    float* out = (float*)d_out;

    float *big;
    __nv_bfloat16 *ah, *al, *bh, *bl, *wh, *wl;
    cudaGetSymbolAddress((void**)&big, g_big);
    cudaGetSymbolAddress((void**)&ah,  g_ah);
    cudaGetSymbolAddress((void**)&al,  g_al);
    cudaGetSymbolAddress((void**)&bh,  g_bh);
    cudaGetSymbolAddress((void**)&bl,  g_bl);
    cudaGetSymbolAddress((void**)&wh,  g_wh);
    cudaGetSymbolAddress((void**)&wl,  g_wl);

    cudaFuncSetAttribute(gemm_tc, cudaFuncAttributeMaxDynamicSharedMemorySize,
                         SMEM_TOTAL);

    cudaMemcpyAsync(out, x, (size_t)MTOT * DIM * sizeof(float),
                    cudaMemcpyDeviceToDevice, 0);

    bias_kernel<<<HEADS, NTOK * NTOK>>>(Hstack, hop, rel);

    // one-time weight splits
    split_kernel<<<(4*WQKV_PER/4 + 255)/256, 256>>>(qkv_w,  wh + WQKV_OFF,  wl + WQKV_OFF,  4*WQKV_PER);
    split_kernel<<<(4*WPROJ_PER/4 + 255)/256, 256>>>(proj_w, wh + WPROJ_OFF, wl + WPROJ_OFF, 4*WPROJ_PER);
    split_kernel<<<(4*WFC1_PER/4 + 255)/256, 256>>>(fc1_w,  wh + WFC1_OFF,  wl + WFC1_OFF,  4*WFC1_PER);
    split_kernel<<<(4*WFC2_PER/4 + 255)/256, 256>>>(fc2_w,  wh + WFC2_OFF,  wl + WFC2_OFF,  4*WFC2_PER);

    for (int d = 0; d < DEPTH; d++) {
        // LN1 -> (ah, al)
        ln_kernel<<<MTOT, 128>>>(out, ln1_g + d*DIM, ln1_b + d*DIM, ah, al);
        // qkv = h @ qkv_w.T + b -> big (fp32)
        gemm_tc<<<dim3(3*DIM/TN, MTOT/TM), 128, SMEM_TOTAL>>>(
            ah, al, wh + WQKV_OFF + (size_t)d*WQKV_PER, wl + WQKV_OFF + (size_t)d*WQKV_PER,
            qkv_b + (size_t)d*3*DIM, nullptr, big, nullptr, nullptr, 3*DIM, DIM, 1);
        // attention -> (ah, al)
        attn_kernel<<<dim3(BATCH, HEADS), 128>>>(big, ah, al);
        // x += attn @ proj_w.T + b
        gemm_tc<<<dim3(DIM/TN, MTOT/TM), 128, SMEM_TOTAL>>>(
            ah, al, wh + WPROJ_OFF + (size_t)d*WPROJ_PER, wl + WPROJ_OFF + (size_t)d*WPROJ_PER,
            proj_b + (size_t)d*DIM, out, out, nullptr, nullptr, DIM, DIM, 3);
        // LN2 -> (ah, al)
        ln_kernel<<<MTOT, 128>>>(out, ln2_g + d*DIM, ln2_b + d*DIM, ah, al);
        // h2 = gelu(h @ fc1_w.T + b) -> (bh, bl)
        gemm_tc<<<dim3(HIDDEN/TN, MTOT/TM), 128, SMEM_TOTAL>>>(
            ah, al, wh + WFC1_OFF + (size_t)d*WFC1_PER, wl + WFC1_OFF + (size_t)d*WFC1_PER,
            fc1_b + (size_t)d*HIDDEN, nullptr, nullptr, bh, bl, HIDDEN, DIM, 2);
        // x += h2 @ fc2_w.T + b
        gemm_tc<<<dim3(DIM/TN, MTOT/TM), 128, SMEM_TOTAL>>>(
            bh, bl, wh + WFC2_OFF + (size_t)d*WFC2_PER, wl + WFC2_OFF + (size_t)d*WFC2_PER,
            fc2_b + (size_t)d*DIM, out, out, nullptr, nullptr, DIM, HIDDEN, 3);
    }
}